// round 1
// baseline (speedup 1.0000x reference)
#include <cuda_runtime.h>

#define S_LEN  4096
#define DMODEL 2048
#define NHEADS 16
#define HD     128

// Scratch: __device__ globals (no allocations allowed anywhere).
__device__ float g_Q[S_LEN * DMODEL];
__device__ float g_K[S_LEN * DMODEL];
__device__ float g_V[S_LEN * DMODEL];
__device__ float g_A[S_LEN * DMODEL];

// ---------------------------------------------------------------------------
// GEMM: C[M,N] = A[M,K] @ W[N,K]^T + bias   (nn.Linear layout, both K-major)
// Tiles: BM=BN=128, BK=16. 256 threads, 8x8 microtile per thread.
// ---------------------------------------------------------------------------
#define BM  128
#define BN  128
#define BKK 16

__device__ __forceinline__ void gemm_body(const float* __restrict__ A,
                                          const float* __restrict__ W,
                                          const float* __restrict__ bias,
                                          float* __restrict__ C,
                                          int M, int N, int K)
{
    __shared__ float As[BKK * BM];   // [k][m]
    __shared__ float Bs[BKK * BN];   // [k][n]

    const int tid = threadIdx.x;
    const int tx = tid & 15;         // col group
    const int ty = tid >> 4;         // row group
    const int row0 = blockIdx.y * BM;
    const int col0 = blockIdx.x * BN;

    const float* Ab = A + (size_t)row0 * K;
    const float* Wb = W + (size_t)col0 * K;

    float acc[8][8];
#pragma unroll
    for (int i = 0; i < 8; i++)
#pragma unroll
        for (int j = 0; j < 8; j++) acc[i][j] = 0.0f;

    for (int kt = 0; kt < K; kt += BKK) {
        // Load 128x16 tiles of A and W, transposed into [k][row] layout.
#pragma unroll
        for (int f = 0; f < 2; f++) {
            int e  = tid + (f << 8);          // 0..511
            int r  = e >> 2;                  // 0..127
            int c4 = (e & 3) << 2;            // 0,4,8,12
            float4 av = *(const float4*)(Ab + (size_t)r * K + kt + c4);
            As[(c4 + 0) * BM + r] = av.x;
            As[(c4 + 1) * BM + r] = av.y;
            As[(c4 + 2) * BM + r] = av.z;
            As[(c4 + 3) * BM + r] = av.w;
            float4 wv = *(const float4*)(Wb + (size_t)r * K + kt + c4);
            Bs[(c4 + 0) * BN + r] = wv.x;
            Bs[(c4 + 1) * BN + r] = wv.y;
            Bs[(c4 + 2) * BN + r] = wv.z;
            Bs[(c4 + 3) * BN + r] = wv.w;
        }
        __syncthreads();

#pragma unroll
        for (int k = 0; k < BKK; k++) {
            float a[8], b[8];
            *(float4*)&a[0] = *(const float4*)&As[k * BM + ty * 8];
            *(float4*)&a[4] = *(const float4*)&As[k * BM + ty * 8 + 4];
            *(float4*)&b[0] = *(const float4*)&Bs[k * BN + tx * 8];
            *(float4*)&b[4] = *(const float4*)&Bs[k * BN + tx * 8 + 4];
#pragma unroll
            for (int i = 0; i < 8; i++)
#pragma unroll
                for (int j = 0; j < 8; j++)
                    acc[i][j] += a[i] * b[j];
        }
        __syncthreads();
    }

    // Epilogue: add bias, vectorized store.
#pragma unroll
    for (int i = 0; i < 8; i++) {
        int row = row0 + ty * 8 + i;
#pragma unroll
        for (int j4 = 0; j4 < 8; j4 += 4) {
            int col = col0 + tx * 8 + j4;
            float4 o;
            o.x = acc[i][j4 + 0] + bias[col + 0];
            o.y = acc[i][j4 + 1] + bias[col + 1];
            o.z = acc[i][j4 + 2] + bias[col + 2];
            o.w = acc[i][j4 + 3] + bias[col + 3];
            *(float4*)(C + (size_t)row * N + col) = o;
        }
    }
}

__global__ void __launch_bounds__(256)
qkv_kernel(const float* __restrict__ x,
           const float* __restrict__ Wq, const float* __restrict__ bq,
           const float* __restrict__ Wk, const float* __restrict__ bk,
           const float* __restrict__ Wv, const float* __restrict__ bv)
{
    const float* W; const float* b; float* C;
    if (blockIdx.z == 0)      { W = Wq; b = bq; C = g_Q; }
    else if (blockIdx.z == 1) { W = Wk; b = bk; C = g_K; }
    else                      { W = Wv; b = bv; C = g_V; }
    gemm_body(x, W, b, C, S_LEN, DMODEL, DMODEL);
}

__global__ void __launch_bounds__(256)
out_kernel(const float* __restrict__ Wo, const float* __restrict__ bo,
           float* __restrict__ out)
{
    gemm_body(g_A, Wo, bo, out, S_LEN, DMODEL, DMODEL);
}

// ---------------------------------------------------------------------------
// Flash attention: per (64-query block, head). 256 threads.
// Q,K stored transposed [k][row] (stride 68) for conflict-free LDS.128;
// V row-major [c][d] (stride 132); P staged via SMEM (stride 68).
// ---------------------------------------------------------------------------
#define BR 64
#define BC 64
#define TKS 68          // transposed stride (64 + 4 pad)
#define VSS 132         // V stride (128 + 4 pad)
#define PSS 68          // P stride (64 + 4 pad)
#define FLASH_SMEM ((2 * HD * TKS + BC * VSS + BR * PSS) * (int)sizeof(float))

__global__ void __launch_bounds__(256) flash_kernel()
{
    extern __shared__ float sm[];
    float* QsT = sm;                     // [HD][TKS]
    float* KsT = QsT + HD * TKS;         // [HD][TKS]
    float* Vs  = KsT + HD * TKS;         // [BC][VSS]
    float* Ps  = Vs + BC * VSS;          // [BR][PSS]

    const int tid = threadIdx.x;
    const int tx = tid & 15;             // col group (keys / head-dim)
    const int ty = tid >> 4;             // row group (queries)
    const int h  = blockIdx.y;
    const int q0 = blockIdx.x * BR;

    const float scale = 0.08838834764831845f;   // 1/sqrt(128)

    // Load Q tile (64x128), pre-scaled, transposed into QsT[k][row].
#pragma unroll
    for (int f = 0; f < 8; f++) {
        int e  = tid + (f << 8);         // 0..2047
        int r  = e >> 5;                 // 0..63
        int k4 = (e & 31) << 2;          // 0..124
        float4 qv = *(const float4*)&g_Q[(size_t)(q0 + r) * DMODEL + h * HD + k4];
        QsT[(k4 + 0) * TKS + r] = qv.x * scale;
        QsT[(k4 + 1) * TKS + r] = qv.y * scale;
        QsT[(k4 + 2) * TKS + r] = qv.z * scale;
        QsT[(k4 + 3) * TKS + r] = qv.w * scale;
    }

    float m[4], l[4], acc[4][8];
#pragma unroll
    for (int i = 0; i < 4; i++) {
        m[i] = -1e30f; l[i] = 0.0f;
#pragma unroll
        for (int d = 0; d < 8; d++) acc[i][d] = 0.0f;
    }

    for (int jt = 0; jt < S_LEN / BC; jt++) {
        __syncthreads();   // protect Vs/Ps from previous iteration's readers

        // Load K (transposed) and V tiles for this KV block.
        const int kv0 = jt * BC;
#pragma unroll
        for (int f = 0; f < 8; f++) {
            int e  = tid + (f << 8);
            int r  = e >> 5;
            int k4 = (e & 31) << 2;
            float4 kv = *(const float4*)&g_K[(size_t)(kv0 + r) * DMODEL + h * HD + k4];
            KsT[(k4 + 0) * TKS + r] = kv.x;
            KsT[(k4 + 1) * TKS + r] = kv.y;
            KsT[(k4 + 2) * TKS + r] = kv.z;
            KsT[(k4 + 3) * TKS + r] = kv.w;
            float4 vv = *(const float4*)&g_V[(size_t)(kv0 + r) * DMODEL + h * HD + k4];
            *(float4*)&Vs[r * VSS + k4] = vv;
        }
        __syncthreads();

        // S = (Q*scale) @ K^T for this 64x64 tile; thread owns s[4][4].
        float s[4][4];
#pragma unroll
        for (int i = 0; i < 4; i++)
#pragma unroll
            for (int j = 0; j < 4; j++) s[i][j] = 0.0f;

#pragma unroll 8
        for (int k = 0; k < HD; k++) {
            float4 q  = *(const float4*)&QsT[k * TKS + ty * 4];
            float4 kk = *(const float4*)&KsT[k * TKS + tx * 4];
            s[0][0] += q.x * kk.x; s[0][1] += q.x * kk.y; s[0][2] += q.x * kk.z; s[0][3] += q.x * kk.w;
            s[1][0] += q.y * kk.x; s[1][1] += q.y * kk.y; s[1][2] += q.y * kk.z; s[1][3] += q.y * kk.w;
            s[2][0] += q.z * kk.x; s[2][1] += q.z * kk.y; s[2][2] += q.z * kk.z; s[2][3] += q.z * kk.w;
            s[3][0] += q.w * kk.x; s[3][1] += q.w * kk.y; s[3][2] += q.w * kk.z; s[3][3] += q.w * kk.w;
        }

        // Online softmax: row reductions across the 16 tx-lanes (same warp half).
#pragma unroll
        for (int i = 0; i < 4; i++) {
            float mx = fmaxf(fmaxf(s[i][0], s[i][1]), fmaxf(s[i][2], s[i][3]));
#pragma unroll
            for (int o = 8; o > 0; o >>= 1)
                mx = fmaxf(mx, __shfl_xor_sync(0xffffffffu, mx, o));
            float nm = fmaxf(m[i], mx);
            float alpha = __expf(m[i] - nm);
            m[i] = nm;
            float rs = 0.0f;
#pragma unroll
            for (int j = 0; j < 4; j++) {
                s[i][j] = __expf(s[i][j] - nm);
                rs += s[i][j];
            }
#pragma unroll
            for (int o = 8; o > 0; o >>= 1)
                rs += __shfl_xor_sync(0xffffffffu, rs, o);
            l[i] = l[i] * alpha + rs;
#pragma unroll
            for (int d = 0; d < 8; d++) acc[i][d] *= alpha;
            *(float4*)&Ps[(ty * 4 + i) * PSS + tx * 4] =
                make_float4(s[i][0], s[i][1], s[i][2], s[i][3]);
        }
        __syncthreads();

        // O += P @ V : thread owns rows ty*4..+3, cols tx*8..+7 of O.
#pragma unroll 2
        for (int c = 0; c < BC; c += 4) {
            float p[4][4];
#pragma unroll
            for (int i = 0; i < 4; i++)
                *(float4*)&p[i][0] = *(const float4*)&Ps[(ty * 4 + i) * PSS + c];
#pragma unroll
            for (int cc = 0; cc < 4; cc++) {
                float4 v0 = *(const float4*)&Vs[(c + cc) * VSS + tx * 8];
                float4 v1 = *(const float4*)&Vs[(c + cc) * VSS + tx * 8 + 4];
#pragma unroll
                for (int i = 0; i < 4; i++) {
                    float pi = p[i][cc];
                    acc[i][0] += pi * v0.x; acc[i][1] += pi * v0.y;
                    acc[i][2] += pi * v0.z; acc[i][3] += pi * v0.w;
                    acc[i][4] += pi * v1.x; acc[i][5] += pi * v1.y;
                    acc[i][6] += pi * v1.z; acc[i][7] += pi * v1.w;
                }
            }
        }
    }

    // Normalize and write attention output (head-interleaved [S, D]).
#pragma unroll
    for (int i = 0; i < 4; i++) {
        float inv = 1.0f / l[i];
        size_t base = (size_t)(q0 + ty * 4 + i) * DMODEL + h * HD + tx * 8;
        float4 o0, o1;
        o0.x = acc[i][0] * inv; o0.y = acc[i][1] * inv;
        o0.z = acc[i][2] * inv; o0.w = acc[i][3] * inv;
        o1.x = acc[i][4] * inv; o1.y = acc[i][5] * inv;
        o1.z = acc[i][6] * inv; o1.w = acc[i][7] * inv;
        *(float4*)&g_A[base]     = o0;
        *(float4*)&g_A[base + 4] = o1;
    }
}

// ---------------------------------------------------------------------------
extern "C" void kernel_launch(void* const* d_in, const int* in_sizes, int n_in,
                              void* d_out, int out_size)
{
    const float* x  = (const float*)d_in[0];
    const float* Wq = (const float*)d_in[1];
    const float* bq = (const float*)d_in[2];
    const float* Wk = (const float*)d_in[3];
    const float* bk = (const float*)d_in[4];
    const float* Wv = (const float*)d_in[5];
    const float* bv = (const float*)d_in[6];
    const float* Wo = (const float*)d_in[7];
    const float* bo = (const float*)d_in[8];
    float* out = (float*)d_out;

    cudaFuncSetAttribute(flash_kernel,
                         cudaFuncAttributeMaxDynamicSharedMemorySize, FLASH_SMEM);

    // 1) Fused Q/K/V projections
    qkv_kernel<<<dim3(DMODEL / BN, S_LEN / BM, 3), 256>>>(x, Wq, bq, Wk, bk, Wv, bv);
    // 2) Flash attention per (query-block, head)
    flash_kernel<<<dim3(S_LEN / BR, NHEADS), 256, FLASH_SMEM>>>();
    // 3) Output projection
    out_kernel<<<dim3(DMODEL / BN, S_LEN / BM), 256>>>(Wo, bo, out);
}

// round 3
// speedup vs baseline: 3.0551x; 3.0551x over previous
#include <cuda_runtime.h>
#include <cuda_bf16.h>
#include <cstdint>

#define S_LEN  4096
#define DMODEL 2048
#define NHEADS 16
#define HD     128

// ---------------------------------------------------------------------------
// Scratch (__device__ globals — no allocations allowed anywhere)
// ---------------------------------------------------------------------------
__device__ __nv_bfloat16 g_xh[S_LEN * DMODEL];
__device__ __nv_bfloat16 g_xl[S_LEN * DMODEL];
__device__ __nv_bfloat16 g_Wh[4][DMODEL * DMODEL];   // q,k,v,o
__device__ __nv_bfloat16 g_Wl[4][DMODEL * DMODEL];
__device__ __nv_bfloat16 g_Qh[S_LEN * DMODEL];
__device__ __nv_bfloat16 g_Ql[S_LEN * DMODEL];
__device__ __nv_bfloat16 g_Kh[S_LEN * DMODEL];
__device__ __nv_bfloat16 g_Kl[S_LEN * DMODEL];
__device__ __nv_bfloat16 g_Vh[S_LEN * DMODEL];
__device__ __nv_bfloat16 g_Vl[S_LEN * DMODEL];
__device__ __nv_bfloat16 g_Ah[S_LEN * DMODEL];
__device__ __nv_bfloat16 g_Al[S_LEN * DMODEL];

// ---------------------------------------------------------------------------
// PTX helpers: mma.sync bf16, ldmatrix, cp.async  (all sm_80+ family-safe)
// ---------------------------------------------------------------------------
__device__ __forceinline__ uint32_t smem_u32(const void* p) {
    uint32_t a;
    asm("{ .reg .u64 t; cvta.to.shared.u64 t, %1; cvt.u32.u64 %0, t; }"
        : "=r"(a) : "l"(p));
    return a;
}

__device__ __forceinline__ void mma_bf16(float* c, const uint32_t* a,
                                         uint32_t b0, uint32_t b1) {
    asm volatile(
        "mma.sync.aligned.m16n8k16.row.col.f32.bf16.bf16.f32 "
        "{%0,%1,%2,%3}, {%4,%5,%6,%7}, {%8,%9}, {%0,%1,%2,%3};"
        : "+f"(c[0]), "+f"(c[1]), "+f"(c[2]), "+f"(c[3])
        : "r"(a[0]), "r"(a[1]), "r"(a[2]), "r"(a[3]), "r"(b0), "r"(b1));
}

__device__ __forceinline__ void ldm_x4(uint32_t* r, uint32_t addr) {
    asm volatile("ldmatrix.sync.aligned.m8n8.x4.shared.b16 {%0,%1,%2,%3}, [%4];"
                 : "=r"(r[0]), "=r"(r[1]), "=r"(r[2]), "=r"(r[3]) : "r"(addr));
}

__device__ __forceinline__ void ldm_x4_t(uint32_t* r, uint32_t addr) {
    asm volatile("ldmatrix.sync.aligned.m8n8.x4.trans.shared.b16 {%0,%1,%2,%3}, [%4];"
                 : "=r"(r[0]), "=r"(r[1]), "=r"(r[2]), "=r"(r[3]) : "r"(addr));
}

__device__ __forceinline__ void g2s16(uint32_t dst, const void* src) {
    asm volatile("cp.async.ca.shared.global [%0], [%1], 16;"
                 :: "r"(dst), "l"(src));
}
__device__ __forceinline__ void cp_commit() {
    asm volatile("cp.async.commit_group;");
}
template<int N> __device__ __forceinline__ void cp_wait() {
    asm volatile("cp.async.wait_group %0;" :: "n"(N));
}

// fast 2^x in FFMA/ALU (no MUFU).  x <= 0 expected; clamped below -125.
__device__ __forceinline__ float fexp2(float x) {
    x = fmaxf(x, -125.0f);
    float t = x + 12582912.0f;           // round-to-int magic (1.5*2^23)
    float f = x - (t - 12582912.0f);     // f in [-0.5, 0.5]
    int   n = __float_as_int(t) - 0x4B400000;
    float p = 1.5403530e-4f;
    p = fmaf(p, f, 1.3333558e-3f);
    p = fmaf(p, f, 9.6181291e-3f);
    p = fmaf(p, f, 5.5504109e-2f);
    p = fmaf(p, f, 2.4022651e-1f);
    p = fmaf(p, f, 6.9314718e-1f);
    p = fmaf(p, f, 1.0f);
    return p * __int_as_float((n + 127) << 23);
}

__device__ __forceinline__ uint32_t packbf(float x, float y) {
    __nv_bfloat162 v = __floats2bfloat162_rn(x, y);   // x -> low half
    return *reinterpret_cast<uint32_t*>(&v);
}
__device__ __forceinline__ void split2(float x, float y, uint32_t& h, uint32_t& l) {
    __nv_bfloat162 vh = __floats2bfloat162_rn(x, y);
    float2 back = __bfloat1622float2(vh);
    __nv_bfloat162 vl = __floats2bfloat162_rn(x - back.x, y - back.y);
    h = *reinterpret_cast<uint32_t*>(&vh);
    l = *reinterpret_cast<uint32_t*>(&vl);
}

// ---------------------------------------------------------------------------
// Split kernel: fp32 -> (bf16 hi, bf16 lo).  sel: 0=x, 1..4=W[sel-1]
// ---------------------------------------------------------------------------
__global__ void __launch_bounds__(256)
split_sel_kernel(const float4* __restrict__ src4, int sel, int n4)
{
    int i = blockIdx.x * 256 + threadIdx.x;
    if (i >= n4) return;
    __nv_bfloat162* hi;
    __nv_bfloat162* lo;
    if (sel == 0) { hi = (__nv_bfloat162*)g_xh; lo = (__nv_bfloat162*)g_xl; }
    else          { hi = (__nv_bfloat162*)g_Wh[sel - 1]; lo = (__nv_bfloat162*)g_Wl[sel - 1]; }
    float4 v = src4[i];
    __nv_bfloat162 h0 = __floats2bfloat162_rn(v.x, v.y);
    __nv_bfloat162 h1 = __floats2bfloat162_rn(v.z, v.w);
    float2 b0 = __bfloat1622float2(h0);
    float2 b1 = __bfloat1622float2(h1);
    hi[2 * i]     = h0;
    hi[2 * i + 1] = h1;
    lo[2 * i]     = __floats2bfloat162_rn(v.x - b0.x, v.y - b0.y);
    lo[2 * i + 1] = __floats2bfloat162_rn(v.z - b1.x, v.w - b1.y);
}

// ---------------------------------------------------------------------------
// Split-bf16 HMMA GEMM: C[M,N] = A[M,K] @ W[N,K]^T + bias
// Block 128x128, BK=32, cp.async double buffer, 8 warps (4m x 2n), m32xn64/warp.
// SMEM rows padded to 80B -> conflict-free ldmatrix.
// ---------------------------------------------------------------------------
#define GBK   32
#define GROWB 80
#define GTILE (128 * GROWB)        // 10240
#define GSTG  (4 * GTILE)          // 40960
#define GEMM_SMEM (2 * GSTG)       // 81920

__device__ __forceinline__ void gemm_issue_tile(uint32_t dst, const __nv_bfloat16* src,
                                                int kc, int tid)
{
#pragma unroll
    for (int j = 0; j < 2; j++) {
        int idx = tid + (j << 8);          // 0..511
        int row = idx >> 2, c = idx & 3;
        g2s16(dst + row * GROWB + c * 16,
              src + (size_t)row * DMODEL + kc + c * 8);
    }
}

template<int SPLIT_OUT>
__device__ __forceinline__ void gemm_mma_body(
    const __nv_bfloat16* __restrict__ Ah, const __nv_bfloat16* __restrict__ Al,
    const __nv_bfloat16* __restrict__ Bh, const __nv_bfloat16* __restrict__ Bl,
    const float* __restrict__ bias,
    float* __restrict__ outF, __nv_bfloat16* __restrict__ outH,
    __nv_bfloat16* __restrict__ outL)
{
    extern __shared__ char sm[];
    const uint32_t sb = smem_u32(sm);
    const int tid = threadIdx.x, wid = tid >> 5, lane = tid & 31;
    const int m0 = blockIdx.y * 128, n0 = blockIdx.x * 128;
    const int wm = wid & 3, wn = wid >> 2;

    const __nv_bfloat16* tA_h = Ah + (size_t)m0 * DMODEL;
    const __nv_bfloat16* tA_l = Al + (size_t)m0 * DMODEL;
    const __nv_bfloat16* tB_h = Bh + (size_t)n0 * DMODEL;
    const __nv_bfloat16* tB_l = Bl + (size_t)n0 * DMODEL;

    float acc[2][8][4];
#pragma unroll
    for (int i = 0; i < 2; i++)
#pragma unroll
        for (int j = 0; j < 8; j++)
#pragma unroll
            for (int k = 0; k < 4; k++) acc[i][j][k] = 0.0f;

    // per-thread ldmatrix address components
    const uint32_t a_off = (uint32_t)((lane & 15) * GROWB + (lane >> 4) * 16);
    const uint32_t b_off = (uint32_t)(((lane & 7) + ((lane >> 4) << 3)) * GROWB
                                      + ((lane >> 3) & 1) * 16);

    // prologue: stage 0
    gemm_issue_tile(sb + 0 * GTILE, tA_h, 0, tid);
    gemm_issue_tile(sb + 1 * GTILE, tA_l, 0, tid);
    gemm_issue_tile(sb + 2 * GTILE, tB_h, 0, tid);
    gemm_issue_tile(sb + 3 * GTILE, tB_l, 0, tid);
    cp_commit();

    const int NCH = DMODEL / GBK;   // 64
    for (int ch = 0; ch < NCH; ch++) {
        if (ch + 1 < NCH) {
            uint32_t d = sb + ((ch + 1) & 1) * GSTG;
            int kc = (ch + 1) * GBK;
            gemm_issue_tile(d + 0 * GTILE, tA_h, kc, tid);
            gemm_issue_tile(d + 1 * GTILE, tA_l, kc, tid);
            gemm_issue_tile(d + 2 * GTILE, tB_h, kc, tid);
            gemm_issue_tile(d + 3 * GTILE, tB_l, kc, tid);
            cp_commit();
            cp_wait<1>();
        } else {
            cp_wait<0>();
        }
        __syncthreads();

        const uint32_t stg = sb + (ch & 1) * GSTG;
        const uint32_t aH_b = stg + 0 * GTILE + (wm * 32) * GROWB + a_off;
        const uint32_t aL_b = stg + 1 * GTILE + (wm * 32) * GROWB + a_off;
        const uint32_t bH_b = stg + 2 * GTILE + (wn * 64) * GROWB + b_off;
        const uint32_t bL_b = stg + 3 * GTILE + (wn * 64) * GROWB + b_off;

#pragma unroll
        for (int ks = 0; ks < 2; ks++) {
            uint32_t aH[2][4], aL[2][4];
#pragma unroll
            for (int mt = 0; mt < 2; mt++) {
                ldm_x4(aH[mt], aH_b + mt * 16 * GROWB + ks * 32);
                ldm_x4(aL[mt], aL_b + mt * 16 * GROWB + ks * 32);
            }
#pragma unroll
            for (int ntp = 0; ntp < 4; ntp++) {
                uint32_t bh[4], bl[4];
                ldm_x4(bh, bH_b + ntp * 16 * GROWB + ks * 32);
                ldm_x4(bl, bL_b + ntp * 16 * GROWB + ks * 32);
#pragma unroll
                for (int mt = 0; mt < 2; mt++) {
                    mma_bf16(acc[mt][2 * ntp],     aH[mt], bh[0], bh[1]);
                    mma_bf16(acc[mt][2 * ntp + 1], aH[mt], bh[2], bh[3]);
                    mma_bf16(acc[mt][2 * ntp],     aH[mt], bl[0], bl[1]);
                    mma_bf16(acc[mt][2 * ntp + 1], aH[mt], bl[2], bl[3]);
                    mma_bf16(acc[mt][2 * ntp],     aL[mt], bh[0], bh[1]);
                    mma_bf16(acc[mt][2 * ntp + 1], aL[mt], bh[2], bh[3]);
                }
            }
        }
        __syncthreads();
    }

    // epilogue
    const int rin = lane >> 2, cin = (lane & 3) * 2;
#pragma unroll
    for (int mt = 0; mt < 2; mt++) {
#pragma unroll
        for (int nt = 0; nt < 8; nt++) {
            int r = m0 + wm * 32 + mt * 16 + rin;
            int c = n0 + wn * 64 + nt * 8 + cin;
            float b0 = bias[c], b1 = bias[c + 1];
            float v0 = acc[mt][nt][0] + b0;
            float v1 = acc[mt][nt][1] + b1;
            float v2 = acc[mt][nt][2] + b0;
            float v3 = acc[mt][nt][3] + b1;
            if (SPLIT_OUT) {
                uint32_t h, l;
                split2(v0, v1, h, l);
                *(uint32_t*)&outH[(size_t)r * DMODEL + c] = h;
                *(uint32_t*)&outL[(size_t)r * DMODEL + c] = l;
                split2(v2, v3, h, l);
                *(uint32_t*)&outH[(size_t)(r + 8) * DMODEL + c] = h;
                *(uint32_t*)&outL[(size_t)(r + 8) * DMODEL + c] = l;
            } else {
                *(float2*)&outF[(size_t)r * DMODEL + c]       = make_float2(v0, v1);
                *(float2*)&outF[(size_t)(r + 8) * DMODEL + c] = make_float2(v2, v3);
            }
        }
    }
}

__global__ void __launch_bounds__(256)
qkv_mma(const float* __restrict__ bq, const float* __restrict__ bk,
        const float* __restrict__ bv)
{
    int z = blockIdx.z;
    const float* bias = (z == 0) ? bq : ((z == 1) ? bk : bv);
    __nv_bfloat16* oh = (z == 0) ? g_Qh : ((z == 1) ? g_Kh : g_Vh);
    __nv_bfloat16* ol = (z == 0) ? g_Ql : ((z == 1) ? g_Kl : g_Vl);
    gemm_mma_body<1>(g_xh, g_xl, g_Wh[z], g_Wl[z], bias, nullptr, oh, ol);
}

__global__ void __launch_bounds__(256)
out_mma(const float* __restrict__ bo, float* __restrict__ out)
{
    gemm_mma_body<0>(g_Ah, g_Al, g_Wh[3], g_Wl[3], bo, out, nullptr, nullptr);
}

// ---------------------------------------------------------------------------
// Flash attention on HMMA: CTA = (128 q-rows, head). 8 warps, m16 rows each.
// 64-key chunks, split-bf16 QK^T and PV, FFMA softmax, cp.async KV pipeline.
// ---------------------------------------------------------------------------
#define FROWB 272
#define QTILE (128 * FROWB)        // 34816
#define KTILE (64 * FROWB)         // 17408
#define KVSTG (4 * KTILE)          // 69632
#define FL_SMEM (2 * QTILE + 2 * KVSTG)   // 208896

__device__ __forceinline__ void fl_issue_tile(uint32_t dst, const __nv_bfloat16* src,
                                              int row0, int coff, int tid)
{
#pragma unroll
    for (int j = 0; j < 4; j++) {
        int idx = tid + (j << 8);          // 0..1023
        int row = idx >> 4, c = idx & 15;
        g2s16(dst + row * FROWB + c * 16,
              src + (size_t)(row0 + row) * DMODEL + coff + c * 8);
    }
}

__global__ void __launch_bounds__(256) flash_mma()
{
    extern __shared__ char sm[];
    const uint32_t sb = smem_u32(sm);
    const int tid = threadIdx.x, wid = tid >> 5, lane = tid & 31;
    const int h = blockIdx.y, q0 = blockIdx.x * 128;
    const int coff = h * HD;

    const uint32_t Qh_s = sb, Ql_s = sb + QTILE;
    const uint32_t KV0  = sb + 2 * QTILE;

    // prologue: Q (hi+lo), then KV chunk 0
#pragma unroll
    for (int j = 0; j < 8; j++) {
        int idx = tid + (j << 8);          // 0..2047
        int row = idx >> 4, c = idx & 15;
        g2s16(Qh_s + row * FROWB + c * 16,
              g_Qh + (size_t)(q0 + row) * DMODEL + coff + c * 8);
        g2s16(Ql_s + row * FROWB + c * 16,
              g_Ql + (size_t)(q0 + row) * DMODEL + coff + c * 8);
    }
    cp_commit();
    fl_issue_tile(KV0 + 0 * KTILE, g_Kh, 0, coff, tid);
    fl_issue_tile(KV0 + 1 * KTILE, g_Kl, 0, coff, tid);
    fl_issue_tile(KV0 + 2 * KTILE, g_Vh, 0, coff, tid);
    fl_issue_tile(KV0 + 3 * KTILE, g_Vl, 0, coff, tid);
    cp_commit();

    float oacc[16][4];
#pragma unroll
    for (int i = 0; i < 16; i++)
#pragma unroll
        for (int j = 0; j < 4; j++) oacc[i][j] = 0.0f;
    float mrow0 = -1e30f, mrow1 = -1e30f, lrow0 = 0.0f, lrow1 = 0.0f;

    const float C = 0.08838834764831845f * 1.4426950408889634f;  // scale*log2(e)

    const int rbase = wid * 16;
    const uint32_t a_off = (uint32_t)((rbase + (lane & 15)) * FROWB + (lane >> 4) * 16);
    const uint32_t b_off = (uint32_t)(((lane & 7) + ((lane >> 4) << 3)) * FROWB
                                      + ((lane >> 3) & 1) * 16);
    const uint32_t v_off = (uint32_t)((lane & 15) * FROWB + (lane >> 4) * 16);

    const int NCH = S_LEN / 64;   // 64
    for (int ch = 0; ch < NCH; ch++) {
        if (ch + 1 < NCH) {
            uint32_t d = KV0 + ((ch + 1) & 1) * KVSTG;
            int kv0 = (ch + 1) * 64;
            fl_issue_tile(d + 0 * KTILE, g_Kh, kv0, coff, tid);
            fl_issue_tile(d + 1 * KTILE, g_Kl, kv0, coff, tid);
            fl_issue_tile(d + 2 * KTILE, g_Vh, kv0, coff, tid);
            fl_issue_tile(d + 3 * KTILE, g_Vl, kv0, coff, tid);
            cp_commit();
            cp_wait<1>();
        } else {
            cp_wait<0>();
        }
        __syncthreads();

        const uint32_t Kh_s = KV0 + (ch & 1) * KVSTG;
        const uint32_t Kl_s = Kh_s + KTILE;
        const uint32_t Vh_s = Kl_s + KTILE;
        const uint32_t Vl_s = Vh_s + KTILE;

        // ---- S = Q K^T (64 keys), split-bf16 ----
        float s[8][4];
#pragma unroll
        for (int i = 0; i < 8; i++)
#pragma unroll
            for (int j = 0; j < 4; j++) s[i][j] = 0.0f;

#pragma unroll
        for (int ks = 0; ks < 8; ks++) {
            uint32_t aH[4], aL[4];
            ldm_x4(aH, Qh_s + a_off + ks * 32);
            ldm_x4(aL, Ql_s + a_off + ks * 32);
#pragma unroll
            for (int ntp = 0; ntp < 4; ntp++) {
                uint32_t bh[4], bl[4];
                uint32_t o = b_off + ntp * 16 * FROWB + ks * 32;
                ldm_x4(bh, Kh_s + o);
                ldm_x4(bl, Kl_s + o);
                mma_bf16(s[2 * ntp],     aH, bh[0], bh[1]);
                mma_bf16(s[2 * ntp + 1], aH, bh[2], bh[3]);
                mma_bf16(s[2 * ntp],     aH, bl[0], bl[1]);
                mma_bf16(s[2 * ntp + 1], aH, bl[2], bl[3]);
                mma_bf16(s[2 * ntp],     aL, bh[0], bh[1]);
                mma_bf16(s[2 * ntp + 1], aL, bh[2], bh[3]);
            }
        }

        // ---- online softmax (rows lane>>2 and +8) ----
        float mx0 = -1e30f, mx1 = -1e30f;
#pragma unroll
        for (int nt = 0; nt < 8; nt++) {
            mx0 = fmaxf(mx0, fmaxf(s[nt][0], s[nt][1]));
            mx1 = fmaxf(mx1, fmaxf(s[nt][2], s[nt][3]));
        }
        mx0 = fmaxf(mx0, __shfl_xor_sync(0xffffffffu, mx0, 1));
        mx0 = fmaxf(mx0, __shfl_xor_sync(0xffffffffu, mx0, 2));
        mx1 = fmaxf(mx1, __shfl_xor_sync(0xffffffffu, mx1, 1));
        mx1 = fmaxf(mx1, __shfl_xor_sync(0xffffffffu, mx1, 2));
        float nm0 = fmaxf(mrow0, mx0), nm1 = fmaxf(mrow1, mx1);
        float al0 = fexp2((mrow0 - nm0) * C), al1 = fexp2((mrow1 - nm1) * C);
        mrow0 = nm0; mrow1 = nm1;
        float rs0 = 0.0f, rs1 = 0.0f;
#pragma unroll
        for (int nt = 0; nt < 8; nt++) {
            s[nt][0] = fexp2((s[nt][0] - nm0) * C);
            s[nt][1] = fexp2((s[nt][1] - nm0) * C);
            s[nt][2] = fexp2((s[nt][2] - nm1) * C);
            s[nt][3] = fexp2((s[nt][3] - nm1) * C);
            rs0 += s[nt][0] + s[nt][1];
            rs1 += s[nt][2] + s[nt][3];
        }
        rs0 += __shfl_xor_sync(0xffffffffu, rs0, 1);
        rs0 += __shfl_xor_sync(0xffffffffu, rs0, 2);
        rs1 += __shfl_xor_sync(0xffffffffu, rs1, 1);
        rs1 += __shfl_xor_sync(0xffffffffu, rs1, 2);
        lrow0 = lrow0 * al0 + rs0;
        lrow1 = lrow1 * al1 + rs1;
#pragma unroll
        for (int nt = 0; nt < 16; nt++) {
            oacc[nt][0] *= al0; oacc[nt][1] *= al0;
            oacc[nt][2] *= al1; oacc[nt][3] *= al1;
        }

        // ---- O += P V, split-bf16 (P fragments stay in registers) ----
#pragma unroll
        for (int ks = 0; ks < 4; ks++) {
            uint32_t pH[4], pL[4];
            split2(s[2 * ks][0],     s[2 * ks][1],     pH[0], pL[0]);
            split2(s[2 * ks][2],     s[2 * ks][3],     pH[1], pL[1]);
            split2(s[2 * ks + 1][0], s[2 * ks + 1][1], pH[2], pL[2]);
            split2(s[2 * ks + 1][2], s[2 * ks + 1][3], pH[3], pL[3]);
#pragma unroll
            for (int dp = 0; dp < 8; dp++) {
                uint32_t bh[4], bl[4];
                uint32_t o = v_off + ks * 16 * FROWB + dp * 32;
                ldm_x4_t(bh, Vh_s + o);
                ldm_x4_t(bl, Vl_s + o);
                mma_bf16(oacc[2 * dp],     pH, bh[0], bh[1]);
                mma_bf16(oacc[2 * dp + 1], pH, bh[2], bh[3]);
                mma_bf16(oacc[2 * dp],     pH, bl[0], bl[1]);
                mma_bf16(oacc[2 * dp + 1], pH, bl[2], bl[3]);
                mma_bf16(oacc[2 * dp],     pL, bh[0], bh[1]);
                mma_bf16(oacc[2 * dp + 1], pL, bh[2], bh[3]);
            }
        }
        __syncthreads();
    }

    // epilogue: normalize, split to bf16 hi/lo, store g_Ah/g_Al
    float inv0 = 1.0f / lrow0, inv1 = 1.0f / lrow1;
    int r0 = q0 + rbase + (lane >> 2);
    int cb = coff + (lane & 3) * 2;
#pragma unroll
    for (int nt = 0; nt < 16; nt++) {
        int c = cb + nt * 8;
        uint32_t hh, ll;
        split2(oacc[nt][0] * inv0, oacc[nt][1] * inv0, hh, ll);
        *(uint32_t*)&g_Ah[(size_t)r0 * DMODEL + c] = hh;
        *(uint32_t*)&g_Al[(size_t)r0 * DMODEL + c] = ll;
        split2(oacc[nt][2] * inv1, oacc[nt][3] * inv1, hh, ll);
        *(uint32_t*)&g_Ah[(size_t)(r0 + 8) * DMODEL + c] = hh;
        *(uint32_t*)&g_Al[(size_t)(r0 + 8) * DMODEL + c] = ll;
    }
}

// ---------------------------------------------------------------------------
extern "C" void kernel_launch(void* const* d_in, const int* in_sizes, int n_in,
                              void* d_out, int out_size)
{
    const float* x  = (const float*)d_in[0];
    const float* Wq = (const float*)d_in[1];
    const float* bq = (const float*)d_in[2];
    const float* Wk = (const float*)d_in[3];
    const float* bk = (const float*)d_in[4];
    const float* Wv = (const float*)d_in[5];
    const float* bv = (const float*)d_in[6];
    const float* Wo = (const float*)d_in[7];
    const float* bo = (const float*)d_in[8];
    float* out = (float*)d_out;

    cudaFuncSetAttribute(qkv_mma,  cudaFuncAttributeMaxDynamicSharedMemorySize, GEMM_SMEM);
    cudaFuncSetAttribute(out_mma,  cudaFuncAttributeMaxDynamicSharedMemorySize, GEMM_SMEM);
    cudaFuncSetAttribute(flash_mma, cudaFuncAttributeMaxDynamicSharedMemorySize, FL_SMEM);

    const int n4x = S_LEN * DMODEL / 4;
    const int n4w = DMODEL * DMODEL / 4;

    split_sel_kernel<<<n4x / 256, 256>>>((const float4*)x,  0, n4x);
    split_sel_kernel<<<n4w / 256, 256>>>((const float4*)Wq, 1, n4w);
    split_sel_kernel<<<n4w / 256, 256>>>((const float4*)Wk, 2, n4w);
    split_sel_kernel<<<n4w / 256, 256>>>((const float4*)Wv, 3, n4w);
    split_sel_kernel<<<n4w / 256, 256>>>((const float4*)Wo, 4, n4w);

    qkv_mma<<<dim3(DMODEL / 128, S_LEN / 128, 3), 256, GEMM_SMEM>>>(bq, bk, bv);
    flash_mma<<<dim3(S_LEN / 128, NHEADS), 256, FL_SMEM>>>();
    out_mma<<<dim3(DMODEL / 128, S_LEN / 128), 256, GEMM_SMEM>>>(bo, out);
}

// round 5
// speedup vs baseline: 4.2055x; 1.3766x over previous
#include <cuda_runtime.h>
#include <cuda_bf16.h>
#include <cuda_fp16.h>
#include <cstdint>

#define S_LEN  4096
#define DMODEL 2048
#define NHEADS 16
#define HD     128

// ---------------------------------------------------------------------------
// Scratch (__device__ globals — no allocations allowed anywhere)
// ---------------------------------------------------------------------------
__device__ __nv_bfloat16 g_xh[S_LEN * DMODEL];
__device__ __nv_bfloat16 g_xl[S_LEN * DMODEL];
__device__ __nv_bfloat16 g_Wh[4][DMODEL * DMODEL];   // q,k,v,o
__device__ __nv_bfloat16 g_Wl[4][DMODEL * DMODEL];
__device__ __half g_Qh16[S_LEN * DMODEL];            // Q * scale * log2e, hi
__device__ __half g_Ql16[S_LEN * DMODEL];            // residual lo
__device__ __half g_K16[S_LEN * DMODEL];             // K single fp16
__device__ __half g_V16[S_LEN * DMODEL];             // V single fp16
__device__ __nv_bfloat16 g_Ah[S_LEN * DMODEL];
__device__ __nv_bfloat16 g_Al[S_LEN * DMODEL];

// ---------------------------------------------------------------------------
// PTX helpers (sm_80+ family-safe)
// ---------------------------------------------------------------------------
__device__ __forceinline__ uint32_t smem_u32(const void* p) {
    uint32_t a;
    asm("{ .reg .u64 t; cvta.to.shared.u64 t, %1; cvt.u32.u64 %0, t; }"
        : "=r"(a) : "l"(p));
    return a;
}

__device__ __forceinline__ void mma_bf16(float* c, const uint32_t* a,
                                         uint32_t b0, uint32_t b1) {
    asm volatile(
        "mma.sync.aligned.m16n8k16.row.col.f32.bf16.bf16.f32 "
        "{%0,%1,%2,%3}, {%4,%5,%6,%7}, {%8,%9}, {%0,%1,%2,%3};"
        : "+f"(c[0]), "+f"(c[1]), "+f"(c[2]), "+f"(c[3])
        : "r"(a[0]), "r"(a[1]), "r"(a[2]), "r"(a[3]), "r"(b0), "r"(b1));
}

__device__ __forceinline__ void mma_f16(float* c, const uint32_t* a,
                                        uint32_t b0, uint32_t b1) {
    asm volatile(
        "mma.sync.aligned.m16n8k16.row.col.f32.f16.f16.f32 "
        "{%0,%1,%2,%3}, {%4,%5,%6,%7}, {%8,%9}, {%0,%1,%2,%3};"
        : "+f"(c[0]), "+f"(c[1]), "+f"(c[2]), "+f"(c[3])
        : "r"(a[0]), "r"(a[1]), "r"(a[2]), "r"(a[3]), "r"(b0), "r"(b1));
}

__device__ __forceinline__ void ldm_x4(uint32_t* r, uint32_t addr) {
    asm volatile("ldmatrix.sync.aligned.m8n8.x4.shared.b16 {%0,%1,%2,%3}, [%4];"
                 : "=r"(r[0]), "=r"(r[1]), "=r"(r[2]), "=r"(r[3]) : "r"(addr));
}

__device__ __forceinline__ void ldm_x4_t(uint32_t* r, uint32_t addr) {
    asm volatile("ldmatrix.sync.aligned.m8n8.x4.trans.shared.b16 {%0,%1,%2,%3}, [%4];"
                 : "=r"(r[0]), "=r"(r[1]), "=r"(r[2]), "=r"(r[3]) : "r"(addr));
}

__device__ __forceinline__ void g2s16(uint32_t dst, const void* src) {
    asm volatile("cp.async.ca.shared.global [%0], [%1], 16;"
                 :: "r"(dst), "l"(src));
}
__device__ __forceinline__ void cp_commit() {
    asm volatile("cp.async.commit_group;");
}
template<int N> __device__ __forceinline__ void cp_wait() {
    asm volatile("cp.async.wait_group %0;" :: "n"(N));
}

// fast 2^x in FFMA/ALU (no MUFU).  x <= 0 expected; clamped below -125.
__device__ __forceinline__ float fexp2(float x) {
    x = fmaxf(x, -125.0f);
    float t = x + 12582912.0f;           // round-to-int magic (1.5*2^23)
    float f = x - (t - 12582912.0f);     // f in [-0.5, 0.5]
    int   n = __float_as_int(t) - 0x4B400000;
    float p = 1.5403530e-4f;
    p = fmaf(p, f, 1.3333558e-3f);
    p = fmaf(p, f, 9.6181291e-3f);
    p = fmaf(p, f, 5.5504109e-2f);
    p = fmaf(p, f, 2.4022651e-1f);
    p = fmaf(p, f, 6.9314718e-1f);
    p = fmaf(p, f, 1.0f);
    return p * __int_as_float((n + 127) << 23);
}

__device__ __forceinline__ void split2(float x, float y, uint32_t& h, uint32_t& l) {
    __nv_bfloat162 vh = __floats2bfloat162_rn(x, y);
    float2 back = __bfloat1622float2(vh);
    __nv_bfloat162 vl = __floats2bfloat162_rn(x - back.x, y - back.y);
    h = *reinterpret_cast<uint32_t*>(&vh);
    l = *reinterpret_cast<uint32_t*>(&vl);
}

__device__ __forceinline__ void split2h(float x, float y, uint32_t& h, uint32_t& l) {
    __half2 vh = __floats2half2_rn(x, y);
    float2 back = __half22float2(vh);
    __half2 vl = __floats2half2_rn(x - back.x, y - back.y);
    h = *reinterpret_cast<uint32_t*>(&vh);
    l = *reinterpret_cast<uint32_t*>(&vl);
}

__device__ __forceinline__ uint32_t packh2(float x, float y) {
    __half2 v = __floats2half2_rn(x, y);
    return *reinterpret_cast<uint32_t*>(&v);
}

// ---------------------------------------------------------------------------
// Split kernel: fp32 -> (bf16 hi, bf16 lo).  sel: 0=x, 1..4=W[sel-1]
// ---------------------------------------------------------------------------
__global__ void __launch_bounds__(256)
split_sel_kernel(const float4* __restrict__ src4, int sel, int n4)
{
    int i = blockIdx.x * 256 + threadIdx.x;
    if (i >= n4) return;
    __nv_bfloat162* hi;
    __nv_bfloat162* lo;
    if (sel == 0) { hi = (__nv_bfloat162*)g_xh; lo = (__nv_bfloat162*)g_xl; }
    else          { hi = (__nv_bfloat162*)g_Wh[sel - 1]; lo = (__nv_bfloat162*)g_Wl[sel - 1]; }
    float4 v = src4[i];
    __nv_bfloat162 h0 = __floats2bfloat162_rn(v.x, v.y);
    __nv_bfloat162 h1 = __floats2bfloat162_rn(v.z, v.w);
    float2 b0 = __bfloat1622float2(h0);
    float2 b1 = __bfloat1622float2(h1);
    hi[2 * i]     = h0;
    hi[2 * i + 1] = h1;
    lo[2 * i]     = __floats2bfloat162_rn(v.x - b0.x, v.y - b0.y);
    lo[2 * i + 1] = __floats2bfloat162_rn(v.z - b1.x, v.w - b1.y);
}

// ---------------------------------------------------------------------------
// Split-bf16 HMMA GEMM: C[M,N] = A[M,K] @ W[N,K]^T + bias
// Block 128x128, BK=32, cp.async double buffer, 8 warps (4m x 2n).
// MODE: 0 = fp32 out, 2 = fp16 split out (scaled), 3 = fp16 single out
// ---------------------------------------------------------------------------
#define GBK   32
#define GROWB 80
#define GTILE (128 * GROWB)        // 10240
#define GSTG  (4 * GTILE)          // 40960
#define GEMM_SMEM (2 * GSTG)       // 81920

#define SCALE_Q (0.08838834764831845f * 1.4426950408889634f)   // 1/sqrt(128)*log2e

__device__ __forceinline__ void gemm_issue_tile(uint32_t dst, const __nv_bfloat16* src,
                                                int kc, int tid)
{
#pragma unroll
    for (int j = 0; j < 2; j++) {
        int idx = tid + (j << 8);          // 0..511
        int row = idx >> 2, c = idx & 3;
        g2s16(dst + row * GROWB + c * 16,
              src + (size_t)row * DMODEL + kc + c * 8);
    }
}

template<int MODE>
__device__ __forceinline__ void gemm_mma_body(
    const __nv_bfloat16* __restrict__ Ah, const __nv_bfloat16* __restrict__ Al,
    const __nv_bfloat16* __restrict__ Bh, const __nv_bfloat16* __restrict__ Bl,
    const float* __restrict__ bias,
    float* __restrict__ outF, __half* __restrict__ outH16,
    __half* __restrict__ outL16, float oscale)
{
    extern __shared__ char sm[];
    const uint32_t sb = smem_u32(sm);
    const int tid = threadIdx.x, wid = tid >> 5, lane = tid & 31;
    const int m0 = blockIdx.y * 128, n0 = blockIdx.x * 128;
    const int wm = wid & 3, wn = wid >> 2;

    const __nv_bfloat16* tA_h = Ah + (size_t)m0 * DMODEL;
    const __nv_bfloat16* tA_l = Al + (size_t)m0 * DMODEL;
    const __nv_bfloat16* tB_h = Bh + (size_t)n0 * DMODEL;
    const __nv_bfloat16* tB_l = Bl + (size_t)n0 * DMODEL;

    float acc[2][8][4];
#pragma unroll
    for (int i = 0; i < 2; i++)
#pragma unroll
        for (int j = 0; j < 8; j++)
#pragma unroll
            for (int k = 0; k < 4; k++) acc[i][j][k] = 0.0f;

    const uint32_t a_off = (uint32_t)((lane & 15) * GROWB + (lane >> 4) * 16);
    const uint32_t b_off = (uint32_t)(((lane & 7) + ((lane >> 4) << 3)) * GROWB
                                      + ((lane >> 3) & 1) * 16);

    gemm_issue_tile(sb + 0 * GTILE, tA_h, 0, tid);
    gemm_issue_tile(sb + 1 * GTILE, tA_l, 0, tid);
    gemm_issue_tile(sb + 2 * GTILE, tB_h, 0, tid);
    gemm_issue_tile(sb + 3 * GTILE, tB_l, 0, tid);
    cp_commit();

    const int NCH = DMODEL / GBK;   // 64
    for (int ch = 0; ch < NCH; ch++) {
        if (ch + 1 < NCH) {
            uint32_t d = sb + ((ch + 1) & 1) * GSTG;
            int kc = (ch + 1) * GBK;
            gemm_issue_tile(d + 0 * GTILE, tA_h, kc, tid);
            gemm_issue_tile(d + 1 * GTILE, tA_l, kc, tid);
            gemm_issue_tile(d + 2 * GTILE, tB_h, kc, tid);
            gemm_issue_tile(d + 3 * GTILE, tB_l, kc, tid);
            cp_commit();
            cp_wait<1>();
        } else {
            cp_wait<0>();
        }
        __syncthreads();

        const uint32_t stg = sb + (ch & 1) * GSTG;
        const uint32_t aH_b = stg + 0 * GTILE + (wm * 32) * GROWB + a_off;
        const uint32_t aL_b = stg + 1 * GTILE + (wm * 32) * GROWB + a_off;
        const uint32_t bH_b = stg + 2 * GTILE + (wn * 64) * GROWB + b_off;
        const uint32_t bL_b = stg + 3 * GTILE + (wn * 64) * GROWB + b_off;

#pragma unroll
        for (int ks = 0; ks < 2; ks++) {
            uint32_t aH[2][4], aL[2][4];
#pragma unroll
            for (int mt = 0; mt < 2; mt++) {
                ldm_x4(aH[mt], aH_b + mt * 16 * GROWB + ks * 32);
                ldm_x4(aL[mt], aL_b + mt * 16 * GROWB + ks * 32);
            }
#pragma unroll
            for (int ntp = 0; ntp < 4; ntp++) {
                uint32_t bh[4], bl[4];
                ldm_x4(bh, bH_b + ntp * 16 * GROWB + ks * 32);
                ldm_x4(bl, bL_b + ntp * 16 * GROWB + ks * 32);
#pragma unroll
                for (int mt = 0; mt < 2; mt++) {
                    mma_bf16(acc[mt][2 * ntp],     aH[mt], bh[0], bh[1]);
                    mma_bf16(acc[mt][2 * ntp + 1], aH[mt], bh[2], bh[3]);
                    mma_bf16(acc[mt][2 * ntp],     aH[mt], bl[0], bl[1]);
                    mma_bf16(acc[mt][2 * ntp + 1], aH[mt], bl[2], bl[3]);
                    mma_bf16(acc[mt][2 * ntp],     aL[mt], bh[0], bh[1]);
                    mma_bf16(acc[mt][2 * ntp + 1], aL[mt], bh[2], bh[3]);
                }
            }
        }
        __syncthreads();
    }

    // epilogue
    const int rin = lane >> 2, cin = (lane & 3) * 2;
#pragma unroll
    for (int mt = 0; mt < 2; mt++) {
#pragma unroll
        for (int nt = 0; nt < 8; nt++) {
            int r = m0 + wm * 32 + mt * 16 + rin;
            int c = n0 + wn * 64 + nt * 8 + cin;
            float b0 = bias[c], b1 = bias[c + 1];
            float v0 = acc[mt][nt][0] + b0;
            float v1 = acc[mt][nt][1] + b1;
            float v2 = acc[mt][nt][2] + b0;
            float v3 = acc[mt][nt][3] + b1;
            if (MODE == 0) {
                *(float2*)&outF[(size_t)r * DMODEL + c]       = make_float2(v0, v1);
                *(float2*)&outF[(size_t)(r + 8) * DMODEL + c] = make_float2(v2, v3);
            } else if (MODE == 2) {
                uint32_t h, l;
                split2h(v0 * oscale, v1 * oscale, h, l);
                *(uint32_t*)&outH16[(size_t)r * DMODEL + c] = h;
                *(uint32_t*)&outL16[(size_t)r * DMODEL + c] = l;
                split2h(v2 * oscale, v3 * oscale, h, l);
                *(uint32_t*)&outH16[(size_t)(r + 8) * DMODEL + c] = h;
                *(uint32_t*)&outL16[(size_t)(r + 8) * DMODEL + c] = l;
            } else {
                *(uint32_t*)&outH16[(size_t)r * DMODEL + c]       = packh2(v0, v1);
                *(uint32_t*)&outH16[(size_t)(r + 8) * DMODEL + c] = packh2(v2, v3);
            }
        }
    }
}

__global__ void __launch_bounds__(256)
qkv_mma(const float* __restrict__ bq, const float* __restrict__ bk,
        const float* __restrict__ bv)
{
    int z = blockIdx.z;
    if (z == 0)
        gemm_mma_body<2>(g_xh, g_xl, g_Wh[0], g_Wl[0], bq, nullptr,
                         g_Qh16, g_Ql16, SCALE_Q);
    else if (z == 1)
        gemm_mma_body<3>(g_xh, g_xl, g_Wh[1], g_Wl[1], bk, nullptr,
                         g_K16, nullptr, 1.0f);
    else
        gemm_mma_body<3>(g_xh, g_xl, g_Wh[2], g_Wl[2], bv, nullptr,
                         g_V16, nullptr, 1.0f);
}

__global__ void __launch_bounds__(256)
out_mma(const float* __restrict__ bo, float* __restrict__ out)
{
    gemm_mma_body<0>(g_Ah, g_Al, g_Wh[3], g_Wl[3], bo, out, nullptr, nullptr, 1.0f);
}

// ---------------------------------------------------------------------------
// Flash attention, fp16 HMMA: CTA = (128 q-rows, head). 8 warps.
// QK^T: Q exact 2-term split vs single K. PV: unsplit P vs single V.
// ---------------------------------------------------------------------------
#define FROWB 272
#define QTILE (128 * FROWB)        // 34816
#define KTILE (64 * FROWB)         // 17408
#define KVSTG (2 * KTILE)          // 34816 (K + V)
#define FL_SMEM (2 * QTILE + 2 * KVSTG)   // 139264

__device__ __forceinline__ void fl_issue_tile(uint32_t dst, const __half* src,
                                              int row0, int coff, int tid)
{
#pragma unroll
    for (int j = 0; j < 4; j++) {
        int idx = tid + (j << 8);          // 0..1023
        int row = idx >> 4, c = idx & 15;
        g2s16(dst + row * FROWB + c * 16,
              src + (size_t)(row0 + row) * DMODEL + coff + c * 8);
    }
}

__global__ void __launch_bounds__(256) flash_mma()
{
    extern __shared__ char sm[];
    const uint32_t sb = smem_u32(sm);
    const int tid = threadIdx.x, wid = tid >> 5, lane = tid & 31;
    const int h = blockIdx.y, q0 = blockIdx.x * 128;
    const int coff = h * HD;

    const uint32_t Qh_s = sb, Ql_s = sb + QTILE;
    const uint32_t KV0  = sb + 2 * QTILE;

    // prologue: Q (hi+lo), then KV chunk 0
#pragma unroll
    for (int j = 0; j < 8; j++) {
        int idx = tid + (j << 8);          // 0..2047
        int row = idx >> 4, c = idx & 15;
        g2s16(Qh_s + row * FROWB + c * 16,
              g_Qh16 + (size_t)(q0 + row) * DMODEL + coff + c * 8);
        g2s16(Ql_s + row * FROWB + c * 16,
              g_Ql16 + (size_t)(q0 + row) * DMODEL + coff + c * 8);
    }
    cp_commit();
    fl_issue_tile(KV0 + 0 * KTILE, g_K16, 0, coff, tid);
    fl_issue_tile(KV0 + 1 * KTILE, g_V16, 0, coff, tid);
    cp_commit();

    float oacc[16][4];
#pragma unroll
    for (int i = 0; i < 16; i++)
#pragma unroll
        for (int j = 0; j < 4; j++) oacc[i][j] = 0.0f;
    float mrow0 = -1e30f, mrow1 = -1e30f, lrow0 = 0.0f, lrow1 = 0.0f;

    const int rbase = wid * 16;
    const uint32_t a_off = (uint32_t)((rbase + (lane & 15)) * FROWB + (lane >> 4) * 16);
    const uint32_t b_off = (uint32_t)(((lane & 7) + ((lane >> 4) << 3)) * FROWB
                                      + ((lane >> 3) & 1) * 16);
    const uint32_t v_off = (uint32_t)((lane & 15) * FROWB + (lane >> 4) * 16);

    const int NCH = S_LEN / 64;   // 64
    for (int ch = 0; ch < NCH; ch++) {
        if (ch + 1 < NCH) {
            uint32_t d = KV0 + ((ch + 1) & 1) * KVSTG;
            int kv0 = (ch + 1) * 64;
            fl_issue_tile(d + 0 * KTILE, g_K16, kv0, coff, tid);
            fl_issue_tile(d + 1 * KTILE, g_V16, kv0, coff, tid);
            cp_commit();
            cp_wait<1>();
        } else {
            cp_wait<0>();
        }
        __syncthreads();

        const uint32_t K_s = KV0 + (ch & 1) * KVSTG;
        const uint32_t V_s = K_s + KTILE;

        // ---- S = Q K^T (64 keys): (Qh + Ql) * K, scores already in log2 units ----
        float s[8][4];
#pragma unroll
        for (int i = 0; i < 8; i++)
#pragma unroll
            for (int j = 0; j < 4; j++) s[i][j] = 0.0f;

#pragma unroll
        for (int ks = 0; ks < 8; ks++) {
            uint32_t aH[4], aL[4];
            ldm_x4(aH, Qh_s + a_off + ks * 32);
            ldm_x4(aL, Ql_s + a_off + ks * 32);
#pragma unroll
            for (int ntp = 0; ntp < 4; ntp++) {
                uint32_t bh[4];
                ldm_x4(bh, K_s + b_off + ntp * 16 * FROWB + ks * 32);
                mma_f16(s[2 * ntp],     aH, bh[0], bh[1]);
                mma_f16(s[2 * ntp + 1], aH, bh[2], bh[3]);
                mma_f16(s[2 * ntp],     aL, bh[0], bh[1]);
                mma_f16(s[2 * ntp + 1], aL, bh[2], bh[3]);
            }
        }

        // ---- online softmax (rows lane>>2 and +8), base-2 domain ----
        float mx0 = -1e30f, mx1 = -1e30f;
#pragma unroll
        for (int nt = 0; nt < 8; nt++) {
            mx0 = fmaxf(mx0, fmaxf(s[nt][0], s[nt][1]));
            mx1 = fmaxf(mx1, fmaxf(s[nt][2], s[nt][3]));
        }
        mx0 = fmaxf(mx0, __shfl_xor_sync(0xffffffffu, mx0, 1));
        mx0 = fmaxf(mx0, __shfl_xor_sync(0xffffffffu, mx0, 2));
        mx1 = fmaxf(mx1, __shfl_xor_sync(0xffffffffu, mx1, 1));
        mx1 = fmaxf(mx1, __shfl_xor_sync(0xffffffffu, mx1, 2));
        float nm0 = fmaxf(mrow0, mx0), nm1 = fmaxf(mrow1, mx1);
        float al0 = fexp2(mrow0 - nm0), al1 = fexp2(mrow1 - nm1);
        mrow0 = nm0; mrow1 = nm1;
        float rs0 = 0.0f, rs1 = 0.0f;
#pragma unroll
        for (int nt = 0; nt < 8; nt++) {
            s[nt][0] = fexp2(s[nt][0] - nm0);
            s[nt][1] = fexp2(s[nt][1] - nm0);
            s[nt][2] = fexp2(s[nt][2] - nm1);
            s[nt][3] = fexp2(s[nt][3] - nm1);
            rs0 += s[nt][0] + s[nt][1];
            rs1 += s[nt][2] + s[nt][3];
        }
        rs0 += __shfl_xor_sync(0xffffffffu, rs0, 1);
        rs0 += __shfl_xor_sync(0xffffffffu, rs0, 2);
        rs1 += __shfl_xor_sync(0xffffffffu, rs1, 1);
        rs1 += __shfl_xor_sync(0xffffffffu, rs1, 2);
        lrow0 = lrow0 * al0 + rs0;
        lrow1 = lrow1 * al1 + rs1;
#pragma unroll
        for (int nt = 0; nt < 16; nt++) {
            oacc[nt][0] *= al0; oacc[nt][1] *= al0;
            oacc[nt][2] *= al1; oacc[nt][3] *= al1;
        }

        // ---- O += P V, unsplit fp16 P ----
#pragma unroll
        for (int ks = 0; ks < 4; ks++) {
            uint32_t pH[4];
            pH[0] = packh2(s[2 * ks][0],     s[2 * ks][1]);
            pH[1] = packh2(s[2 * ks][2],     s[2 * ks][3]);
            pH[2] = packh2(s[2 * ks + 1][0], s[2 * ks + 1][1]);
            pH[3] = packh2(s[2 * ks + 1][2], s[2 * ks + 1][3]);
#pragma unroll
            for (int dp = 0; dp < 8; dp++) {
                uint32_t bh[4];
                ldm_x4_t(bh, V_s + v_off + ks * 16 * FROWB + dp * 32);
                mma_f16(oacc[2 * dp],     pH, bh[0], bh[1]);
                mma_f16(oacc[2 * dp + 1], pH, bh[2], bh[3]);
            }
        }
        __syncthreads();
    }

    // epilogue: normalize, split to bf16 hi/lo for O-projection
    float inv0 = 1.0f / lrow0, inv1 = 1.0f / lrow1;
    int r0 = q0 + rbase + (lane >> 2);
    int cb = coff + (lane & 3) * 2;
#pragma unroll
    for (int nt = 0; nt < 16; nt++) {
        int c = cb + nt * 8;
        uint32_t hh, ll;
        split2(oacc[nt][0] * inv0, oacc[nt][1] * inv0, hh, ll);
        *(uint32_t*)&g_Ah[(size_t)r0 * DMODEL + c] = hh;
        *(uint32_t*)&g_Al[(size_t)r0 * DMODEL + c] = ll;
        split2(oacc[nt][2] * inv1, oacc[nt][3] * inv1, hh, ll);
        *(uint32_t*)&g_Ah[(size_t)(r0 + 8) * DMODEL + c] = hh;
        *(uint32_t*)&g_Al[(size_t)(r0 + 8) * DMODEL + c] = ll;
    }
}

// ---------------------------------------------------------------------------
extern "C" void kernel_launch(void* const* d_in, const int* in_sizes, int n_in,
                              void* d_out, int out_size)
{
    const float* x  = (const float*)d_in[0];
    const float* Wq = (const float*)d_in[1];
    const float* bq = (const float*)d_in[2];
    const float* Wk = (const float*)d_in[3];
    const float* bk = (const float*)d_in[4];
    const float* Wv = (const float*)d_in[5];
    const float* bv = (const float*)d_in[6];
    const float* Wo = (const float*)d_in[7];
    const float* bo = (const float*)d_in[8];
    float* out = (float*)d_out;

    cudaFuncSetAttribute(qkv_mma,   cudaFuncAttributeMaxDynamicSharedMemorySize, GEMM_SMEM);
    cudaFuncSetAttribute(out_mma,   cudaFuncAttributeMaxDynamicSharedMemorySize, GEMM_SMEM);
    cudaFuncSetAttribute(flash_mma, cudaFuncAttributeMaxDynamicSharedMemorySize, FL_SMEM);

    const int n4x = S_LEN * DMODEL / 4;
    const int n4w = DMODEL * DMODEL / 4;

    split_sel_kernel<<<n4x / 256, 256>>>((const float4*)x,  0, n4x);
    split_sel_kernel<<<n4w / 256, 256>>>((const float4*)Wq, 1, n4w);
    split_sel_kernel<<<n4w / 256, 256>>>((const float4*)Wk, 2, n4w);
    split_sel_kernel<<<n4w / 256, 256>>>((const float4*)Wv, 3, n4w);
    split_sel_kernel<<<n4w / 256, 256>>>((const float4*)Wo, 4, n4w);

    qkv_mma<<<dim3(DMODEL / 128, S_LEN / 128, 3), 256, GEMM_SMEM>>>(bq, bk, bv);
    flash_mma<<<dim3(S_LEN / 128, NHEADS), 256, FL_SMEM>>>();
    out_mma<<<dim3(DMODEL / 128, S_LEN / 128), 256, GEMM_SMEM>>>(bo, out);
}

// round 6
// speedup vs baseline: 4.8888x; 1.1625x over previous
#include <cuda_runtime.h>
#include <cuda_bf16.h>
#include <cuda_fp16.h>
#include <cstdint>

#define S_LEN  4096
#define DMODEL 2048
#define NHEADS 16
#define HD     128

// ---------------------------------------------------------------------------
// Scratch (__device__ globals — no allocations allowed anywhere)
// ---------------------------------------------------------------------------
__device__ __half g_xh16[S_LEN * DMODEL];            // x exact fp16 split hi
__device__ __half g_xl16[S_LEN * DMODEL];            // x residual lo
__device__ __half g_W16[4][DMODEL * DMODEL];         // q,k,v,o weights, single fp16
__device__ __half g_Qh16[S_LEN * DMODEL];            // Q * scale * log2e, hi
__device__ __half g_Ql16[S_LEN * DMODEL];            // residual lo
__device__ __half g_K16[S_LEN * DMODEL];             // K single fp16
__device__ __half g_V16[S_LEN * DMODEL];             // V single fp16
__device__ __half g_Ah16[S_LEN * DMODEL];            // attn out exact fp16 split hi
__device__ __half g_Al16[S_LEN * DMODEL];            // attn out residual lo

// ---------------------------------------------------------------------------
// PTX helpers (sm_80+ family-safe)
// ---------------------------------------------------------------------------
__device__ __forceinline__ uint32_t smem_u32(const void* p) {
    uint32_t a;
    asm("{ .reg .u64 t; cvta.to.shared.u64 t, %1; cvt.u32.u64 %0, t; }"
        : "=r"(a) : "l"(p));
    return a;
}

__device__ __forceinline__ void mma_f16(float* c, const uint32_t* a,
                                        uint32_t b0, uint32_t b1) {
    asm volatile(
        "mma.sync.aligned.m16n8k16.row.col.f32.f16.f16.f32 "
        "{%0,%1,%2,%3}, {%4,%5,%6,%7}, {%8,%9}, {%0,%1,%2,%3};"
        : "+f"(c[0]), "+f"(c[1]), "+f"(c[2]), "+f"(c[3])
        : "r"(a[0]), "r"(a[1]), "r"(a[2]), "r"(a[3]), "r"(b0), "r"(b1));
}

__device__ __forceinline__ void ldm_x4(uint32_t* r, uint32_t addr) {
    asm volatile("ldmatrix.sync.aligned.m8n8.x4.shared.b16 {%0,%1,%2,%3}, [%4];"
                 : "=r"(r[0]), "=r"(r[1]), "=r"(r[2]), "=r"(r[3]) : "r"(addr));
}

__device__ __forceinline__ void ldm_x4_t(uint32_t* r, uint32_t addr) {
    asm volatile("ldmatrix.sync.aligned.m8n8.x4.trans.shared.b16 {%0,%1,%2,%3}, [%4];"
                 : "=r"(r[0]), "=r"(r[1]), "=r"(r[2]), "=r"(r[3]) : "r"(addr));
}

__device__ __forceinline__ void g2s16(uint32_t dst, const void* src) {
    asm volatile("cp.async.ca.shared.global [%0], [%1], 16;"
                 :: "r"(dst), "l"(src));
}
__device__ __forceinline__ void cp_commit() {
    asm volatile("cp.async.commit_group;");
}
template<int N> __device__ __forceinline__ void cp_wait() {
    asm volatile("cp.async.wait_group %0;" :: "n"(N));
}

// fast 2^x in FFMA/ALU (no MUFU).  x <= 0 expected; clamped below -125.
__device__ __forceinline__ float fexp2(float x) {
    x = fmaxf(x, -125.0f);
    float t = x + 12582912.0f;           // round-to-int magic (1.5*2^23)
    float f = x - (t - 12582912.0f);     // f in [-0.5, 0.5]
    int   n = __float_as_int(t) - 0x4B400000;
    float p = 1.5403530e-4f;
    p = fmaf(p, f, 1.3333558e-3f);
    p = fmaf(p, f, 9.6181291e-3f);
    p = fmaf(p, f, 5.5504109e-2f);
    p = fmaf(p, f, 2.4022651e-1f);
    p = fmaf(p, f, 6.9314718e-1f);
    p = fmaf(p, f, 1.0f);
    return p * __int_as_float((n + 127) << 23);
}

__device__ __forceinline__ void split2h(float x, float y, uint32_t& h, uint32_t& l) {
    __half2 vh = __floats2half2_rn(x, y);
    float2 back = __half22float2(vh);
    __half2 vl = __floats2half2_rn(x - back.x, y - back.y);
    h = *reinterpret_cast<uint32_t*>(&vh);
    l = *reinterpret_cast<uint32_t*>(&vl);
}

__device__ __forceinline__ uint32_t packh2(float x, float y) {
    __half2 v = __floats2half2_rn(x, y);
    return *reinterpret_cast<uint32_t*>(&v);
}

// ---------------------------------------------------------------------------
// Split kernel: sel 0 -> x exact fp16 hi/lo; sel 1..4 -> W[sel-1] single fp16
// ---------------------------------------------------------------------------
__global__ void __launch_bounds__(256)
split_sel_kernel(const float4* __restrict__ src4, int sel, int n4)
{
    int i = blockIdx.x * 256 + threadIdx.x;
    if (i >= n4) return;
    float4 v = src4[i];
    if (sel == 0) {
        __half2* hi = (__half2*)g_xh16;
        __half2* lo = (__half2*)g_xl16;
        __half2 h0 = __floats2half2_rn(v.x, v.y);
        __half2 h1 = __floats2half2_rn(v.z, v.w);
        float2 b0 = __half22float2(h0);
        float2 b1 = __half22float2(h1);
        hi[2 * i]     = h0;
        hi[2 * i + 1] = h1;
        lo[2 * i]     = __floats2half2_rn(v.x - b0.x, v.y - b0.y);
        lo[2 * i + 1] = __floats2half2_rn(v.z - b1.x, v.w - b1.y);
    } else {
        __half2* w = (__half2*)g_W16[sel - 1];
        w[2 * i]     = __floats2half2_rn(v.x, v.y);
        w[2 * i + 1] = __floats2half2_rn(v.z, v.w);
    }
}

// ---------------------------------------------------------------------------
// 2-MMA fp16 GEMM: C[M,N] = (Ah+Al)[M,K] @ W16[N,K]^T + bias
// Block 128x128, BK=32, cp.async double buffer, 8 warps (4m x 2n).
// MODE: 0 = fp32 out, 2 = fp16 split out (scaled), 3 = fp16 single out
// ---------------------------------------------------------------------------
#define GBK   32
#define GROWB 80
#define GTILE (128 * GROWB)        // 10240
#define GSTG  (3 * GTILE)          // 30720 (Ah, Al, W)
#define GEMM_SMEM (2 * GSTG)       // 61440

#define SCALE_Q (0.08838834764831845f * 1.4426950408889634f)   // 1/sqrt(128)*log2e

__device__ __forceinline__ void gemm_issue_tile(uint32_t dst, const __half* src,
                                                int kc, int tid)
{
#pragma unroll
    for (int j = 0; j < 2; j++) {
        int idx = tid + (j << 8);          // 0..511
        int row = idx >> 2, c = idx & 3;
        g2s16(dst + row * GROWB + c * 16,
              src + (size_t)row * DMODEL + kc + c * 8);
    }
}

template<int MODE>
__device__ __forceinline__ void gemm_mma_body(
    const __half* __restrict__ Ah, const __half* __restrict__ Al,
    const __half* __restrict__ B,
    const float* __restrict__ bias,
    float* __restrict__ outF, __half* __restrict__ outH16,
    __half* __restrict__ outL16, float oscale)
{
    extern __shared__ char sm[];
    const uint32_t sb = smem_u32(sm);
    const int tid = threadIdx.x, wid = tid >> 5, lane = tid & 31;
    const int m0 = blockIdx.y * 128, n0 = blockIdx.x * 128;
    const int wm = wid & 3, wn = wid >> 2;

    const __half* tA_h = Ah + (size_t)m0 * DMODEL;
    const __half* tA_l = Al + (size_t)m0 * DMODEL;
    const __half* tB   = B  + (size_t)n0 * DMODEL;

    float acc[2][8][4];
#pragma unroll
    for (int i = 0; i < 2; i++)
#pragma unroll
        for (int j = 0; j < 8; j++)
#pragma unroll
            for (int k = 0; k < 4; k++) acc[i][j][k] = 0.0f;

    const uint32_t a_off = (uint32_t)((lane & 15) * GROWB + (lane >> 4) * 16);
    const uint32_t b_off = (uint32_t)(((lane & 7) + ((lane >> 4) << 3)) * GROWB
                                      + ((lane >> 3) & 1) * 16);

    gemm_issue_tile(sb + 0 * GTILE, tA_h, 0, tid);
    gemm_issue_tile(sb + 1 * GTILE, tA_l, 0, tid);
    gemm_issue_tile(sb + 2 * GTILE, tB,   0, tid);
    cp_commit();

    const int NCH = DMODEL / GBK;   // 64
    for (int ch = 0; ch < NCH; ch++) {
        if (ch + 1 < NCH) {
            uint32_t d = sb + ((ch + 1) & 1) * GSTG;
            int kc = (ch + 1) * GBK;
            gemm_issue_tile(d + 0 * GTILE, tA_h, kc, tid);
            gemm_issue_tile(d + 1 * GTILE, tA_l, kc, tid);
            gemm_issue_tile(d + 2 * GTILE, tB,   kc, tid);
            cp_commit();
            cp_wait<1>();
        } else {
            cp_wait<0>();
        }
        __syncthreads();

        const uint32_t stg = sb + (ch & 1) * GSTG;
        const uint32_t aH_b = stg + 0 * GTILE + (wm * 32) * GROWB + a_off;
        const uint32_t aL_b = stg + 1 * GTILE + (wm * 32) * GROWB + a_off;
        const uint32_t bS_b = stg + 2 * GTILE + (wn * 64) * GROWB + b_off;

#pragma unroll
        for (int ks = 0; ks < 2; ks++) {
            uint32_t aH[2][4], aL[2][4];
#pragma unroll
            for (int mt = 0; mt < 2; mt++) {
                ldm_x4(aH[mt], aH_b + mt * 16 * GROWB + ks * 32);
                ldm_x4(aL[mt], aL_b + mt * 16 * GROWB + ks * 32);
            }
#pragma unroll
            for (int ntp = 0; ntp < 4; ntp++) {
                uint32_t bh[4];
                ldm_x4(bh, bS_b + ntp * 16 * GROWB + ks * 32);
#pragma unroll
                for (int mt = 0; mt < 2; mt++) {
                    mma_f16(acc[mt][2 * ntp],     aH[mt], bh[0], bh[1]);
                    mma_f16(acc[mt][2 * ntp + 1], aH[mt], bh[2], bh[3]);
                    mma_f16(acc[mt][2 * ntp],     aL[mt], bh[0], bh[1]);
                    mma_f16(acc[mt][2 * ntp + 1], aL[mt], bh[2], bh[3]);
                }
            }
        }
        __syncthreads();
    }

    // epilogue
    const int rin = lane >> 2, cin = (lane & 3) * 2;
#pragma unroll
    for (int mt = 0; mt < 2; mt++) {
#pragma unroll
        for (int nt = 0; nt < 8; nt++) {
            int r = m0 + wm * 32 + mt * 16 + rin;
            int c = n0 + wn * 64 + nt * 8 + cin;
            float b0 = bias[c], b1 = bias[c + 1];
            float v0 = acc[mt][nt][0] + b0;
            float v1 = acc[mt][nt][1] + b1;
            float v2 = acc[mt][nt][2] + b0;
            float v3 = acc[mt][nt][3] + b1;
            if (MODE == 0) {
                *(float2*)&outF[(size_t)r * DMODEL + c]       = make_float2(v0, v1);
                *(float2*)&outF[(size_t)(r + 8) * DMODEL + c] = make_float2(v2, v3);
            } else if (MODE == 2) {
                uint32_t h, l;
                split2h(v0 * oscale, v1 * oscale, h, l);
                *(uint32_t*)&outH16[(size_t)r * DMODEL + c] = h;
                *(uint32_t*)&outL16[(size_t)r * DMODEL + c] = l;
                split2h(v2 * oscale, v3 * oscale, h, l);
                *(uint32_t*)&outH16[(size_t)(r + 8) * DMODEL + c] = h;
                *(uint32_t*)&outL16[(size_t)(r + 8) * DMODEL + c] = l;
            } else {
                *(uint32_t*)&outH16[(size_t)r * DMODEL + c]       = packh2(v0, v1);
                *(uint32_t*)&outH16[(size_t)(r + 8) * DMODEL + c] = packh2(v2, v3);
            }
        }
    }
}

__global__ void __launch_bounds__(256)
qkv_mma(const float* __restrict__ bq, const float* __restrict__ bk,
        const float* __restrict__ bv)
{
    int z = blockIdx.z;
    if (z == 0)
        gemm_mma_body<2>(g_xh16, g_xl16, g_W16[0], bq, nullptr,
                         g_Qh16, g_Ql16, SCALE_Q);
    else if (z == 1)
        gemm_mma_body<3>(g_xh16, g_xl16, g_W16[1], bk, nullptr,
                         g_K16, nullptr, 1.0f);
    else
        gemm_mma_body<3>(g_xh16, g_xl16, g_W16[2], bv, nullptr,
                         g_V16, nullptr, 1.0f);
}

__global__ void __launch_bounds__(256)
out_mma(const float* __restrict__ bo, float* __restrict__ out)
{
    gemm_mma_body<0>(g_Ah16, g_Al16, g_W16[3], bo, out, nullptr, nullptr, 1.0f);
}

// ---------------------------------------------------------------------------
// Flash attention, fp16 HMMA: CTA = (128 q-rows, head). 8 warps.
// QK^T: Q exact 2-term split vs single K. PV: unsplit P vs single V.
// ---------------------------------------------------------------------------
#define FROWB 272
#define QTILE (128 * FROWB)        // 34816
#define KTILE (64 * FROWB)         // 17408
#define KVSTG (2 * KTILE)          // 34816 (K + V)
#define FL_SMEM (2 * QTILE + 2 * KVSTG)   // 139264

__device__ __forceinline__ void fl_issue_tile(uint32_t dst, const __half* src,
                                              int row0, int coff, int tid)
{
#pragma unroll
    for (int j = 0; j < 4; j++) {
        int idx = tid + (j << 8);          // 0..1023
        int row = idx >> 4, c = idx & 15;
        g2s16(dst + row * FROWB + c * 16,
              src + (size_t)(row0 + row) * DMODEL + coff + c * 8);
    }
}

__global__ void __launch_bounds__(256) flash_mma()
{
    extern __shared__ char sm[];
    const uint32_t sb = smem_u32(sm);
    const int tid = threadIdx.x, wid = tid >> 5, lane = tid & 31;
    const int h = blockIdx.y, q0 = blockIdx.x * 128;
    const int coff = h * HD;

    const uint32_t Qh_s = sb, Ql_s = sb + QTILE;
    const uint32_t KV0  = sb + 2 * QTILE;

    // prologue: Q (hi+lo), then KV chunk 0
#pragma unroll
    for (int j = 0; j < 8; j++) {
        int idx = tid + (j << 8);          // 0..2047
        int row = idx >> 4, c = idx & 15;
        g2s16(Qh_s + row * FROWB + c * 16,
              g_Qh16 + (size_t)(q0 + row) * DMODEL + coff + c * 8);
        g2s16(Ql_s + row * FROWB + c * 16,
              g_Ql16 + (size_t)(q0 + row) * DMODEL + coff + c * 8);
    }
    cp_commit();
    fl_issue_tile(KV0 + 0 * KTILE, g_K16, 0, coff, tid);
    fl_issue_tile(KV0 + 1 * KTILE, g_V16, 0, coff, tid);
    cp_commit();

    float oacc[16][4];
#pragma unroll
    for (int i = 0; i < 16; i++)
#pragma unroll
        for (int j = 0; j < 4; j++) oacc[i][j] = 0.0f;
    float mrow0 = -1e30f, mrow1 = -1e30f, lrow0 = 0.0f, lrow1 = 0.0f;

    const int rbase = wid * 16;
    const uint32_t a_off = (uint32_t)((rbase + (lane & 15)) * FROWB + (lane >> 4) * 16);
    const uint32_t b_off = (uint32_t)(((lane & 7) + ((lane >> 4) << 3)) * FROWB
                                      + ((lane >> 3) & 1) * 16);
    const uint32_t v_off = (uint32_t)((lane & 15) * FROWB + (lane >> 4) * 16);

    const int NCH = S_LEN / 64;   // 64
    for (int ch = 0; ch < NCH; ch++) {
        if (ch + 1 < NCH) {
            uint32_t d = KV0 + ((ch + 1) & 1) * KVSTG;
            int kv0 = (ch + 1) * 64;
            fl_issue_tile(d + 0 * KTILE, g_K16, kv0, coff, tid);
            fl_issue_tile(d + 1 * KTILE, g_V16, kv0, coff, tid);
            cp_commit();
            cp_wait<1>();
        } else {
            cp_wait<0>();
        }
        __syncthreads();

        const uint32_t K_s = KV0 + (ch & 1) * KVSTG;
        const uint32_t V_s = K_s + KTILE;

        // ---- S = Q K^T (64 keys): (Qh + Ql) * K, scores already in log2 units ----
        float s[8][4];
#pragma unroll
        for (int i = 0; i < 8; i++)
#pragma unroll
            for (int j = 0; j < 4; j++) s[i][j] = 0.0f;

#pragma unroll
        for (int ks = 0; ks < 8; ks++) {
            uint32_t aH[4], aL[4];
            ldm_x4(aH, Qh_s + a_off + ks * 32);
            ldm_x4(aL, Ql_s + a_off + ks * 32);
#pragma unroll
            for (int ntp = 0; ntp < 4; ntp++) {
                uint32_t bh[4];
                ldm_x4(bh, K_s + b_off + ntp * 16 * FROWB + ks * 32);
                mma_f16(s[2 * ntp],     aH, bh[0], bh[1]);
                mma_f16(s[2 * ntp + 1], aH, bh[2], bh[3]);
                mma_f16(s[2 * ntp],     aL, bh[0], bh[1]);
                mma_f16(s[2 * ntp + 1], aL, bh[2], bh[3]);
            }
        }

        // ---- online softmax (rows lane>>2 and +8), base-2 domain ----
        float mx0 = -1e30f, mx1 = -1e30f;
#pragma unroll
        for (int nt = 0; nt < 8; nt++) {
            mx0 = fmaxf(mx0, fmaxf(s[nt][0], s[nt][1]));
            mx1 = fmaxf(mx1, fmaxf(s[nt][2], s[nt][3]));
        }
        mx0 = fmaxf(mx0, __shfl_xor_sync(0xffffffffu, mx0, 1));
        mx0 = fmaxf(mx0, __shfl_xor_sync(0xffffffffu, mx0, 2));
        mx1 = fmaxf(mx1, __shfl_xor_sync(0xffffffffu, mx1, 1));
        mx1 = fmaxf(mx1, __shfl_xor_sync(0xffffffffu, mx1, 2));
        float nm0 = fmaxf(mrow0, mx0), nm1 = fmaxf(mrow1, mx1);
        float al0 = fexp2(mrow0 - nm0), al1 = fexp2(mrow1 - nm1);
        mrow0 = nm0; mrow1 = nm1;
        float rs0 = 0.0f, rs1 = 0.0f;
#pragma unroll
        for (int nt = 0; nt < 8; nt++) {
            s[nt][0] = fexp2(s[nt][0] - nm0);
            s[nt][1] = fexp2(s[nt][1] - nm0);
            s[nt][2] = fexp2(s[nt][2] - nm1);
            s[nt][3] = fexp2(s[nt][3] - nm1);
            rs0 += s[nt][0] + s[nt][1];
            rs1 += s[nt][2] + s[nt][3];
        }
        rs0 += __shfl_xor_sync(0xffffffffu, rs0, 1);
        rs0 += __shfl_xor_sync(0xffffffffu, rs0, 2);
        rs1 += __shfl_xor_sync(0xffffffffu, rs1, 1);
        rs1 += __shfl_xor_sync(0xffffffffu, rs1, 2);
        lrow0 = lrow0 * al0 + rs0;
        lrow1 = lrow1 * al1 + rs1;
#pragma unroll
        for (int nt = 0; nt < 16; nt++) {
            oacc[nt][0] *= al0; oacc[nt][1] *= al0;
            oacc[nt][2] *= al1; oacc[nt][3] *= al1;
        }

        // ---- O += P V, unsplit fp16 P ----
#pragma unroll
        for (int ks = 0; ks < 4; ks++) {
            uint32_t pH[4];
            pH[0] = packh2(s[2 * ks][0],     s[2 * ks][1]);
            pH[1] = packh2(s[2 * ks][2],     s[2 * ks][3]);
            pH[2] = packh2(s[2 * ks + 1][0], s[2 * ks + 1][1]);
            pH[3] = packh2(s[2 * ks + 1][2], s[2 * ks + 1][3]);
#pragma unroll
            for (int dp = 0; dp < 8; dp++) {
                uint32_t bh[4];
                ldm_x4_t(bh, V_s + v_off + ks * 16 * FROWB + dp * 32);
                mma_f16(oacc[2 * dp],     pH, bh[0], bh[1]);
                mma_f16(oacc[2 * dp + 1], pH, bh[2], bh[3]);
            }
        }
        __syncthreads();
    }

    // epilogue: normalize, exact fp16 split for O-projection
    float inv0 = 1.0f / lrow0, inv1 = 1.0f / lrow1;
    int r0 = q0 + rbase + (lane >> 2);
    int cb = coff + (lane & 3) * 2;
#pragma unroll
    for (int nt = 0; nt < 16; nt++) {
        int c = cb + nt * 8;
        uint32_t hh, ll;
        split2h(oacc[nt][0] * inv0, oacc[nt][1] * inv0, hh, ll);
        *(uint32_t*)&g_Ah16[(size_t)r0 * DMODEL + c] = hh;
        *(uint32_t*)&g_Al16[(size_t)r0 * DMODEL + c] = ll;
        split2h(oacc[nt][2] * inv1, oacc[nt][3] * inv1, hh, ll);
        *(uint32_t*)&g_Ah16[(size_t)(r0 + 8) * DMODEL + c] = hh;
        *(uint32_t*)&g_Al16[(size_t)(r0 + 8) * DMODEL + c] = ll;
    }
}

// ---------------------------------------------------------------------------
extern "C" void kernel_launch(void* const* d_in, const int* in_sizes, int n_in,
                              void* d_out, int out_size)
{
    const float* x  = (const float*)d_in[0];
    const float* Wq = (const float*)d_in[1];
    const float* bq = (const float*)d_in[2];
    const float* Wk = (const float*)d_in[3];
    const float* bk = (const float*)d_in[4];
    const float* Wv = (const float*)d_in[5];
    const float* bv = (const float*)d_in[6];
    const float* Wo = (const float*)d_in[7];
    const float* bo = (const float*)d_in[8];
    float* out = (float*)d_out;

    cudaFuncSetAttribute(qkv_mma,   cudaFuncAttributeMaxDynamicSharedMemorySize, GEMM_SMEM);
    cudaFuncSetAttribute(out_mma,   cudaFuncAttributeMaxDynamicSharedMemorySize, GEMM_SMEM);
    cudaFuncSetAttribute(flash_mma, cudaFuncAttributeMaxDynamicSharedMemorySize, FL_SMEM);

    const int n4x = S_LEN * DMODEL / 4;
    const int n4w = DMODEL * DMODEL / 4;

    split_sel_kernel<<<n4x / 256, 256>>>((const float4*)x,  0, n4x);
    split_sel_kernel<<<n4w / 256, 256>>>((const float4*)Wq, 1, n4w);
    split_sel_kernel<<<n4w / 256, 256>>>((const float4*)Wk, 2, n4w);
    split_sel_kernel<<<n4w / 256, 256>>>((const float4*)Wv, 3, n4w);
    split_sel_kernel<<<n4w / 256, 256>>>((const float4*)Wo, 4, n4w);

    qkv_mma<<<dim3(DMODEL / 128, S_LEN / 128, 3), 256, GEMM_SMEM>>>(bq, bk, bv);
    flash_mma<<<dim3(S_LEN / 128, NHEADS), 256, FL_SMEM>>>();
    out_mma<<<dim3(DMODEL / 128, S_LEN / 128), 256, GEMM_SMEM>>>(bo, out);
}

// round 10
// speedup vs baseline: 5.9317x; 1.2133x over previous
#include <cuda_runtime.h>
#include <cuda_bf16.h>
#include <cuda_fp16.h>
#include <cstdint>

#define S_LEN  4096
#define DMODEL 2048
#define NHEADS 16
#define HD     128

// ---------------------------------------------------------------------------
// Scratch (__device__ globals — no allocations allowed anywhere)
// ---------------------------------------------------------------------------
__device__ __half g_x16[S_LEN * DMODEL];             // x single fp16
__device__ __half g_W16[4][DMODEL * DMODEL];         // q,k,v,o weights, single fp16
__device__ __half g_Qh16[S_LEN * DMODEL];            // Q * scale * log2e, hi
__device__ __half g_Ql16[S_LEN * DMODEL];            // residual lo
__device__ __half g_K16[S_LEN * DMODEL];             // K single fp16
__device__ __half g_V16[S_LEN * DMODEL];             // V single fp16
__device__ __half g_Ah16[S_LEN * DMODEL];            // attn out exact fp16 split hi
__device__ __half g_Al16[S_LEN * DMODEL];            // attn out residual lo

// ---------------------------------------------------------------------------
// PTX helpers (sm_80+ family-safe)
// ---------------------------------------------------------------------------
__device__ __forceinline__ uint32_t smem_u32(const void* p) {
    uint32_t a;
    asm("{ .reg .u64 t; cvta.to.shared.u64 t, %1; cvt.u32.u64 %0, t; }"
        : "=r"(a) : "l"(p));
    return a;
}

__device__ __forceinline__ void mma_f16(float* c, const uint32_t* a,
                                        uint32_t b0, uint32_t b1) {
    asm volatile(
        "mma.sync.aligned.m16n8k16.row.col.f32.f16.f16.f32 "
        "{%0,%1,%2,%3}, {%4,%5,%6,%7}, {%8,%9}, {%0,%1,%2,%3};"
        : "+f"(c[0]), "+f"(c[1]), "+f"(c[2]), "+f"(c[3])
        : "r"(a[0]), "r"(a[1]), "r"(a[2]), "r"(a[3]), "r"(b0), "r"(b1));
}

__device__ __forceinline__ void ldm_x4(uint32_t* r, uint32_t addr) {
    asm volatile("ldmatrix.sync.aligned.m8n8.x4.shared.b16 {%0,%1,%2,%3}, [%4];"
                 : "=r"(r[0]), "=r"(r[1]), "=r"(r[2]), "=r"(r[3]) : "r"(addr));
}

__device__ __forceinline__ void ldm_x4_t(uint32_t* r, uint32_t addr) {
    asm volatile("ldmatrix.sync.aligned.m8n8.x4.trans.shared.b16 {%0,%1,%2,%3}, [%4];"
                 : "=r"(r[0]), "=r"(r[1]), "=r"(r[2]), "=r"(r[3]) : "r"(addr));
}

__device__ __forceinline__ void g2s16(uint32_t dst, const void* src) {
    asm volatile("cp.async.ca.shared.global [%0], [%1], 16;"
                 :: "r"(dst), "l"(src));
}
__device__ __forceinline__ void cp_commit() {
    asm volatile("cp.async.commit_group;");
}
template<int N> __device__ __forceinline__ void cp_wait() {
    asm volatile("cp.async.wait_group %0;" :: "n"(N));
}

// fast 2^x in FFMA/ALU (no MUFU).  x <= 0 expected; clamped below -125.
__device__ __forceinline__ float fexp2(float x) {
    x = fmaxf(x, -125.0f);
    float t = x + 12582912.0f;           // round-to-int magic (1.5*2^23)
    float f = x - (t - 12582912.0f);     // f in [-0.5, 0.5]
    int   n = __float_as_int(t) - 0x4B400000;
    float p = 1.5403530e-4f;
    p = fmaf(p, f, 1.3333558e-3f);
    p = fmaf(p, f, 9.6181291e-3f);
    p = fmaf(p, f, 5.5504109e-2f);
    p = fmaf(p, f, 2.4022651e-1f);
    p = fmaf(p, f, 6.9314718e-1f);
    p = fmaf(p, f, 1.0f);
    return p * __int_as_float((n + 127) << 23);
}

__device__ __forceinline__ void split2h(float x, float y, uint32_t& h, uint32_t& l) {
    __half2 vh = __floats2half2_rn(x, y);
    float2 back = __half22float2(vh);
    __half2 vl = __floats2half2_rn(x - back.x, y - back.y);
    h = *reinterpret_cast<uint32_t*>(&vh);
    l = *reinterpret_cast<uint32_t*>(&vl);
}

__device__ __forceinline__ uint32_t packh2(float x, float y) {
    __half2 v = __floats2half2_rn(x, y);
    return *reinterpret_cast<uint32_t*>(&v);
}

// ---------------------------------------------------------------------------
// Convert kernel: fp32 -> single fp16.  sel: 0=x, 1..4=W[sel-1]
// ---------------------------------------------------------------------------
__global__ void __launch_bounds__(256)
tofp16_kernel(const float4* __restrict__ src4, int sel, int n4)
{
    int i = blockIdx.x * 256 + threadIdx.x;
    if (i >= n4) return;
    float4 v = src4[i];
    __half2* dst = (sel == 0) ? (__half2*)g_x16 : (__half2*)g_W16[sel - 1];
    dst[2 * i]     = __floats2half2_rn(v.x, v.y);
    dst[2 * i + 1] = __floats2half2_rn(v.z, v.w);
}

// ---------------------------------------------------------------------------
// fp16 HMMA GEMM: C[M,N] = (Ah [+ Al])[M,K] @ W16[N,K]^T + bias
// Block 128x128, BK=32, cp.async double buffer, 8 warps (4m x 2n).
// MODE: 0 = fp32 out, 2 = fp16 split out (scaled), 3 = fp16 single out
// ASPLIT: 1 = A has an exact lo-residual operand (2 MMAs), 0 = single A (1 MMA)
// ---------------------------------------------------------------------------
#define GBK   32
#define GROWB 80
#define GTILE (128 * GROWB)        // 10240
#define GEMM_SMEM2 (2 * 2 * GTILE) // 40960 (single-A)
#define GEMM_SMEM3 (2 * 3 * GTILE) // 61440 (split-A)

#define SCALE_Q (0.08838834764831845f * 1.4426950408889634f)   // 1/sqrt(128)*log2e

__device__ __forceinline__ void gemm_issue_tile(uint32_t dst, const __half* src,
                                                int kc, int tid)
{
#pragma unroll
    for (int j = 0; j < 2; j++) {
        int idx = tid + (j << 8);          // 0..511
        int row = idx >> 2, c = idx & 3;
        g2s16(dst + row * GROWB + c * 16,
              src + (size_t)row * DMODEL + kc + c * 8);
    }
}

template<int MODE, int ASPLIT>
__device__ __forceinline__ void gemm_mma_body(
    const __half* __restrict__ Ah, const __half* __restrict__ Al,
    const __half* __restrict__ B,
    const float* __restrict__ bias,
    float* __restrict__ outF, __half* __restrict__ outH16,
    __half* __restrict__ outL16, float oscale)
{
    extern __shared__ char sm[];
    const uint32_t sb = smem_u32(sm);
    const int tid = threadIdx.x, wid = tid >> 5, lane = tid & 31;
    const int m0 = blockIdx.y * 128, n0 = blockIdx.x * 128;
    const int wm = wid & 3, wn = wid >> 2;
    const int NT = 2 + ASPLIT;               // tiles per stage
    const uint32_t STG = (uint32_t)(NT * GTILE);

    const __half* tA_h = Ah + (size_t)m0 * DMODEL;
    const __half* tA_l = ASPLIT ? (Al + (size_t)m0 * DMODEL) : nullptr;
    const __half* tB   = B  + (size_t)n0 * DMODEL;

    float acc[2][8][4];
#pragma unroll
    for (int i = 0; i < 2; i++)
#pragma unroll
        for (int j = 0; j < 8; j++)
#pragma unroll
            for (int k = 0; k < 4; k++) acc[i][j][k] = 0.0f;

    const uint32_t a_off = (uint32_t)((lane & 15) * GROWB + (lane >> 4) * 16);
    const uint32_t b_off = (uint32_t)(((lane & 7) + ((lane >> 4) << 3)) * GROWB
                                      + ((lane >> 3) & 1) * 16);

    gemm_issue_tile(sb + 0 * GTILE, tA_h, 0, tid);
    if (ASPLIT) gemm_issue_tile(sb + 1 * GTILE, tA_l, 0, tid);
    gemm_issue_tile(sb + (1 + ASPLIT) * GTILE, tB, 0, tid);
    cp_commit();

    const int NCH = DMODEL / GBK;   // 64
    for (int ch = 0; ch < NCH; ch++) {
        if (ch + 1 < NCH) {
            uint32_t d = sb + ((ch + 1) & 1) * STG;
            int kc = (ch + 1) * GBK;
            gemm_issue_tile(d + 0 * GTILE, tA_h, kc, tid);
            if (ASPLIT) gemm_issue_tile(d + 1 * GTILE, tA_l, kc, tid);
            gemm_issue_tile(d + (1 + ASPLIT) * GTILE, tB, kc, tid);
            cp_commit();
            cp_wait<1>();
        } else {
            cp_wait<0>();
        }
        __syncthreads();

        const uint32_t stg = sb + (ch & 1) * STG;
        const uint32_t aH_b = stg + 0 * GTILE + (wm * 32) * GROWB + a_off;
        const uint32_t aL_b = stg + 1 * GTILE + (wm * 32) * GROWB + a_off;
        const uint32_t bS_b = stg + (1 + ASPLIT) * GTILE + (wn * 64) * GROWB + b_off;

#pragma unroll
        for (int ks = 0; ks < 2; ks++) {
            uint32_t aH[2][4], aL[2][4];
#pragma unroll
            for (int mt = 0; mt < 2; mt++) {
                ldm_x4(aH[mt], aH_b + mt * 16 * GROWB + ks * 32);
                if (ASPLIT) ldm_x4(aL[mt], aL_b + mt * 16 * GROWB + ks * 32);
            }
#pragma unroll
            for (int ntp = 0; ntp < 4; ntp++) {
                uint32_t bh[4];
                ldm_x4(bh, bS_b + ntp * 16 * GROWB + ks * 32);
#pragma unroll
                for (int mt = 0; mt < 2; mt++) {
                    mma_f16(acc[mt][2 * ntp],     aH[mt], bh[0], bh[1]);
                    mma_f16(acc[mt][2 * ntp + 1], aH[mt], bh[2], bh[3]);
                    if (ASPLIT) {
                        mma_f16(acc[mt][2 * ntp],     aL[mt], bh[0], bh[1]);
                        mma_f16(acc[mt][2 * ntp + 1], aL[mt], bh[2], bh[3]);
                    }
                }
            }
        }
        __syncthreads();
    }

    // epilogue
    const int rin = lane >> 2, cin = (lane & 3) * 2;
#pragma unroll
    for (int mt = 0; mt < 2; mt++) {
#pragma unroll
        for (int nt = 0; nt < 8; nt++) {
            int r = m0 + wm * 32 + mt * 16 + rin;
            int c = n0 + wn * 64 + nt * 8 + cin;
            float b0 = bias[c], b1 = bias[c + 1];
            float v0 = acc[mt][nt][0] + b0;
            float v1 = acc[mt][nt][1] + b1;
            float v2 = acc[mt][nt][2] + b0;
            float v3 = acc[mt][nt][3] + b1;
            if (MODE == 0) {
                *(float2*)&outF[(size_t)r * DMODEL + c]       = make_float2(v0, v1);
                *(float2*)&outF[(size_t)(r + 8) * DMODEL + c] = make_float2(v2, v3);
            } else if (MODE == 2) {
                uint32_t h, l;
                split2h(v0 * oscale, v1 * oscale, h, l);
                *(uint32_t*)&outH16[(size_t)r * DMODEL + c] = h;
                *(uint32_t*)&outL16[(size_t)r * DMODEL + c] = l;
                split2h(v2 * oscale, v3 * oscale, h, l);
                *(uint32_t*)&outH16[(size_t)(r + 8) * DMODEL + c] = h;
                *(uint32_t*)&outL16[(size_t)(r + 8) * DMODEL + c] = l;
            } else {
                *(uint32_t*)&outH16[(size_t)r * DMODEL + c]       = packh2(v0, v1);
                *(uint32_t*)&outH16[(size_t)(r + 8) * DMODEL + c] = packh2(v2, v3);
            }
        }
    }
}

__global__ void __launch_bounds__(256)
qkv_mma(const float* __restrict__ bq, const float* __restrict__ bk,
        const float* __restrict__ bv)
{
    int z = blockIdx.z;
    if (z == 0)
        gemm_mma_body<2, 0>(g_x16, nullptr, g_W16[0], bq, nullptr,
                            g_Qh16, g_Ql16, SCALE_Q);
    else if (z == 1)
        gemm_mma_body<3, 0>(g_x16, nullptr, g_W16[1], bk, nullptr,
                            g_K16, nullptr, 1.0f);
    else
        gemm_mma_body<3, 0>(g_x16, nullptr, g_W16[2], bv, nullptr,
                            g_V16, nullptr, 1.0f);
}

__global__ void __launch_bounds__(256)
out_mma(const float* __restrict__ bo, float* __restrict__ out)
{
    gemm_mma_body<0, 1>(g_Ah16, g_Al16, g_W16[3], bo, out, nullptr, nullptr, 1.0f);
}

// ---------------------------------------------------------------------------
// Flash attention, fp16 HMMA: CTA = (128 q-rows, head). 8 warps.
// QK^T: Q exact 2-term split vs single K. PV: unsplit P vs single V.
// ---------------------------------------------------------------------------
#define FROWB 272
#define QTILE (128 * FROWB)        // 34816
#define KTILE (64 * FROWB)         // 17408
#define KVSTG (2 * KTILE)          // 34816 (K + V)
#define FL_SMEM (2 * QTILE + 2 * KVSTG)   // 139264

__device__ __forceinline__ void fl_issue_tile(uint32_t dst, const __half* src,
                                              int row0, int coff, int tid)
{
#pragma unroll
    for (int j = 0; j < 4; j++) {
        int idx = tid + (j << 8);          // 0..1023
        int row = idx >> 4, c = idx & 15;
        g2s16(dst + row * FROWB + c * 16,
              src + (size_t)(row0 + row) * DMODEL + coff + c * 8);
    }
}

__global__ void __launch_bounds__(256) flash_mma()
{
    extern __shared__ char sm[];
    const uint32_t sb = smem_u32(sm);
    const int tid = threadIdx.x, wid = tid >> 5, lane = tid & 31;
    const int h = blockIdx.y, q0 = blockIdx.x * 128;
    const int coff = h * HD;

    const uint32_t Qh_s = sb, Ql_s = sb + QTILE;
    const uint32_t KV0  = sb + 2 * QTILE;

    // prologue: Q (hi+lo), then KV chunk 0
#pragma unroll
    for (int j = 0; j < 8; j++) {
        int idx = tid + (j << 8);          // 0..2047
        int row = idx >> 4, c = idx & 15;
        g2s16(Qh_s + row * FROWB + c * 16,
              g_Qh16 + (size_t)(q0 + row) * DMODEL + coff + c * 8);
        g2s16(Ql_s + row * FROWB + c * 16,
              g_Ql16 + (size_t)(q0 + row) * DMODEL + coff + c * 8);
    }
    cp_commit();
    fl_issue_tile(KV0 + 0 * KTILE, g_K16, 0, coff, tid);
    fl_issue_tile(KV0 + 1 * KTILE, g_V16, 0, coff, tid);
    cp_commit();

    float oacc[16][4];
#pragma unroll
    for (int i = 0; i < 16; i++)
#pragma unroll
        for (int j = 0; j < 4; j++) oacc[i][j] = 0.0f;
    float mrow0 = -1e30f, mrow1 = -1e30f, lrow0 = 0.0f, lrow1 = 0.0f;

    const int rbase = wid * 16;
    const uint32_t a_off = (uint32_t)((rbase + (lane & 15)) * FROWB + (lane >> 4) * 16);
    const uint32_t b_off = (uint32_t)(((lane & 7) + ((lane >> 4) << 3)) * FROWB
                                      + ((lane >> 3) & 1) * 16);
    const uint32_t v_off = (uint32_t)((lane & 15) * FROWB + (lane >> 4) * 16);

    const int NCH = S_LEN / 64;   // 64
    for (int ch = 0; ch < NCH; ch++) {
        if (ch + 1 < NCH) {
            uint32_t d = KV0 + ((ch + 1) & 1) * KVSTG;
            int kv0 = (ch + 1) * 64;
            fl_issue_tile(d + 0 * KTILE, g_K16, kv0, coff, tid);
            fl_issue_tile(d + 1 * KTILE, g_V16, kv0, coff, tid);
            cp_commit();
            cp_wait<1>();
        } else {
            cp_wait<0>();
        }
        __syncthreads();

        const uint32_t K_s = KV0 + (ch & 1) * KVSTG;
        const uint32_t V_s = K_s + KTILE;

        // ---- S = Q K^T (64 keys): (Qh + Ql) * K, scores already in log2 units ----
        float s[8][4];
#pragma unroll
        for (int i = 0; i < 8; i++)
#pragma unroll
            for (int j = 0; j < 4; j++) s[i][j] = 0.0f;

#pragma unroll
        for (int ks = 0; ks < 8; ks++) {
            uint32_t aH[4], aL[4];
            ldm_x4(aH, Qh_s + a_off + ks * 32);
            ldm_x4(aL, Ql_s + a_off + ks * 32);
#pragma unroll
            for (int ntp = 0; ntp < 4; ntp++) {
                uint32_t bh[4];
                ldm_x4(bh, K_s + b_off + ntp * 16 * FROWB + ks * 32);
                mma_f16(s[2 * ntp],     aH, bh[0], bh[1]);
                mma_f16(s[2 * ntp + 1], aH, bh[2], bh[3]);
                mma_f16(s[2 * ntp],     aL, bh[0], bh[1]);
                mma_f16(s[2 * ntp + 1], aL, bh[2], bh[3]);
            }
        }

        // ---- online softmax (rows lane>>2 and +8), base-2 domain ----
        float mx0 = -1e30f, mx1 = -1e30f;
#pragma unroll
        for (int nt = 0; nt < 8; nt++) {
            mx0 = fmaxf(mx0, fmaxf(s[nt][0], s[nt][1]));
            mx1 = fmaxf(mx1, fmaxf(s[nt][2], s[nt][3]));
        }
        mx0 = fmaxf(mx0, __shfl_xor_sync(0xffffffffu, mx0, 1));
        mx0 = fmaxf(mx0, __shfl_xor_sync(0xffffffffu, mx0, 2));
        mx1 = fmaxf(mx1, __shfl_xor_sync(0xffffffffu, mx1, 1));
        mx1 = fmaxf(mx1, __shfl_xor_sync(0xffffffffu, mx1, 2));
        float nm0 = fmaxf(mrow0, mx0), nm1 = fmaxf(mrow1, mx1);
        float al0 = fexp2(mrow0 - nm0), al1 = fexp2(mrow1 - nm1);
        mrow0 = nm0; mrow1 = nm1;
        float rs0 = 0.0f, rs1 = 0.0f;
#pragma unroll
        for (int nt = 0; nt < 8; nt++) {
            s[nt][0] = fexp2(s[nt][0] - nm0);
            s[nt][1] = fexp2(s[nt][1] - nm0);
            s[nt][2] = fexp2(s[nt][2] - nm1);
            s[nt][3] = fexp2(s[nt][3] - nm1);
            rs0 += s[nt][0] + s[nt][1];
            rs1 += s[nt][2] + s[nt][3];
        }
        rs0 += __shfl_xor_sync(0xffffffffu, rs0, 1);
        rs0 += __shfl_xor_sync(0xffffffffu, rs0, 2);
        rs1 += __shfl_xor_sync(0xffffffffu, rs1, 1);
        rs1 += __shfl_xor_sync(0xffffffffu, rs1, 2);
        lrow0 = lrow0 * al0 + rs0;
        lrow1 = lrow1 * al1 + rs1;
#pragma unroll
        for (int nt = 0; nt < 16; nt++) {
            oacc[nt][0] *= al0; oacc[nt][1] *= al0;
            oacc[nt][2] *= al1; oacc[nt][3] *= al1;
        }

        // ---- O += P V, unsplit fp16 P ----
#pragma unroll
        for (int ks = 0; ks < 4; ks++) {
            uint32_t pH[4];
            pH[0] = packh2(s[2 * ks][0],     s[2 * ks][1]);
            pH[1] = packh2(s[2 * ks][2],     s[2 * ks][3]);
            pH[2] = packh2(s[2 * ks + 1][0], s[2 * ks + 1][1]);
            pH[3] = packh2(s[2 * ks + 1][2], s[2 * ks + 1][3]);
#pragma unroll
            for (int dp = 0; dp < 8; dp++) {
                uint32_t bh[4];
                ldm_x4_t(bh, V_s + v_off + ks * 16 * FROWB + dp * 32);
                mma_f16(oacc[2 * dp],     pH, bh[0], bh[1]);
                mma_f16(oacc[2 * dp + 1], pH, bh[2], bh[3]);
            }
        }
        __syncthreads();
    }

    // epilogue: normalize, exact fp16 split for O-projection
    float inv0 = 1.0f / lrow0, inv1 = 1.0f / lrow1;
    int r0 = q0 + rbase + (lane >> 2);
    int cb = coff + (lane & 3) * 2;
#pragma unroll
    for (int nt = 0; nt < 16; nt++) {
        int c = cb + nt * 8;
        uint32_t hh, ll;
        split2h(oacc[nt][0] * inv0, oacc[nt][1] * inv0, hh, ll);
        *(uint32_t*)&g_Ah16[(size_t)r0 * DMODEL + c] = hh;
        *(uint32_t*)&g_Al16[(size_t)r0 * DMODEL + c] = ll;
        split2h(oacc[nt][2] * inv1, oacc[nt][3] * inv1, hh, ll);
        *(uint32_t*)&g_Ah16[(size_t)(r0 + 8) * DMODEL + c] = hh;
        *(uint32_t*)&g_Al16[(size_t)(r0 + 8) * DMODEL + c] = ll;
    }
}

// ---------------------------------------------------------------------------
extern "C" void kernel_launch(void* const* d_in, const int* in_sizes, int n_in,
                              void* d_out, int out_size)
{
    const float* x  = (const float*)d_in[0];
    const float* Wq = (const float*)d_in[1];
    const float* bq = (const float*)d_in[2];
    const float* Wk = (const float*)d_in[3];
    const float* bk = (const float*)d_in[4];
    const float* Wv = (const float*)d_in[5];
    const float* bv = (const float*)d_in[6];
    const float* Wo = (const float*)d_in[7];
    const float* bo = (const float*)d_in[8];
    float* out = (float*)d_out;

    cudaFuncSetAttribute(qkv_mma,   cudaFuncAttributeMaxDynamicSharedMemorySize, GEMM_SMEM2);
    cudaFuncSetAttribute(out_mma,   cudaFuncAttributeMaxDynamicSharedMemorySize, GEMM_SMEM3);
    cudaFuncSetAttribute(flash_mma, cudaFuncAttributeMaxDynamicSharedMemorySize, FL_SMEM);

    const int n4x = S_LEN * DMODEL / 4;
    const int n4w = DMODEL * DMODEL / 4;

    tofp16_kernel<<<n4x / 256, 256>>>((const float4*)x,  0, n4x);
    tofp16_kernel<<<n4w / 256, 256>>>((const float4*)Wq, 1, n4w);
    tofp16_kernel<<<n4w / 256, 256>>>((const float4*)Wk, 2, n4w);
    tofp16_kernel<<<n4w / 256, 256>>>((const float4*)Wv, 3, n4w);
    tofp16_kernel<<<n4w / 256, 256>>>((const float4*)Wo, 4, n4w);

    qkv_mma<<<dim3(DMODEL / 128, S_LEN / 128, 3), 256, GEMM_SMEM2>>>(bq, bk, bv);
    flash_mma<<<dim3(S_LEN / 128, NHEADS), 256, FL_SMEM>>>();
    out_mma<<<dim3(DMODEL / 128, S_LEN / 128), 256, GEMM_SMEM3>>>(bo, out);
}

// round 15
// speedup vs baseline: 6.4075x; 1.0802x over previous
#include <cuda_runtime.h>
#include <cuda_bf16.h>
#include <cuda_fp16.h>
#include <cstdint>

#define S_LEN  4096
#define DMODEL 2048
#define NHEADS 16
#define HD     128

// ---------------------------------------------------------------------------
// Scratch (__device__ globals — no allocations allowed anywhere)
// ---------------------------------------------------------------------------
__device__ __half g_x16[S_LEN * DMODEL];             // x single fp16
__device__ __half g_W16[4][DMODEL * DMODEL];         // q,k,v,o weights, single fp16
__device__ __half g_Q16[S_LEN * DMODEL];             // Q * scale * log2e, single fp16
__device__ __half g_K16[S_LEN * DMODEL];             // K single fp16
__device__ __half g_V16[S_LEN * DMODEL];             // V single fp16
__device__ __half g_Ah16[S_LEN * DMODEL];            // attn out exact fp16 split hi
__device__ __half g_Al16[S_LEN * DMODEL];            // attn out residual lo

// ---------------------------------------------------------------------------
// PTX helpers (sm_80+ family-safe)
// ---------------------------------------------------------------------------
__device__ __forceinline__ uint32_t smem_u32(const void* p) {
    uint32_t a;
    asm("{ .reg .u64 t; cvta.to.shared.u64 t, %1; cvt.u32.u64 %0, t; }"
        : "=r"(a) : "l"(p));
    return a;
}

__device__ __forceinline__ void mma_f16(float* c, const uint32_t* a,
                                        uint32_t b0, uint32_t b1) {
    asm volatile(
        "mma.sync.aligned.m16n8k16.row.col.f32.f16.f16.f32 "
        "{%0,%1,%2,%3}, {%4,%5,%6,%7}, {%8,%9}, {%0,%1,%2,%3};"
        : "+f"(c[0]), "+f"(c[1]), "+f"(c[2]), "+f"(c[3])
        : "r"(a[0]), "r"(a[1]), "r"(a[2]), "r"(a[3]), "r"(b0), "r"(b1));
}

__device__ __forceinline__ void ldm_x4(uint32_t* r, uint32_t addr) {
    asm volatile("ldmatrix.sync.aligned.m8n8.x4.shared.b16 {%0,%1,%2,%3}, [%4];"
                 : "=r"(r[0]), "=r"(r[1]), "=r"(r[2]), "=r"(r[3]) : "r"(addr));
}

__device__ __forceinline__ void ldm_x4_t(uint32_t* r, uint32_t addr) {
    asm volatile("ldmatrix.sync.aligned.m8n8.x4.trans.shared.b16 {%0,%1,%2,%3}, [%4];"
                 : "=r"(r[0]), "=r"(r[1]), "=r"(r[2]), "=r"(r[3]) : "r"(addr));
}

__device__ __forceinline__ void g2s16(uint32_t dst, const void* src) {
    asm volatile("cp.async.ca.shared.global [%0], [%1], 16;"
                 :: "r"(dst), "l"(src));
}
__device__ __forceinline__ void cp_commit() {
    asm volatile("cp.async.commit_group;");
}
template<int N> __device__ __forceinline__ void cp_wait() {
    asm volatile("cp.async.wait_group %0;" :: "n"(N));
}

// fast 2^x in FFMA/ALU (no MUFU).  x <= 0 expected; clamped below -125.
__device__ __forceinline__ float fexp2(float x) {
    x = fmaxf(x, -125.0f);
    float t = x + 12582912.0f;           // round-to-int magic (1.5*2^23)
    float f = x - (t - 12582912.0f);     // f in [-0.5, 0.5]
    int   n = __float_as_int(t) - 0x4B400000;
    float p = 1.5403530e-4f;
    p = fmaf(p, f, 1.3333558e-3f);
    p = fmaf(p, f, 9.6181291e-3f);
    p = fmaf(p, f, 5.5504109e-2f);
    p = fmaf(p, f, 2.4022651e-1f);
    p = fmaf(p, f, 6.9314718e-1f);
    p = fmaf(p, f, 1.0f);
    return p * __int_as_float((n + 127) << 23);
}

__device__ __forceinline__ void split2h(float x, float y, uint32_t& h, uint32_t& l) {
    __half2 vh = __floats2half2_rn(x, y);
    float2 back = __half22float2(vh);
    __half2 vl = __floats2half2_rn(x - back.x, y - back.y);
    h = *reinterpret_cast<uint32_t*>(&vh);
    l = *reinterpret_cast<uint32_t*>(&vl);
}

__device__ __forceinline__ uint32_t packh2(float x, float y) {
    __half2 v = __floats2half2_rn(x, y);
    return *reinterpret_cast<uint32_t*>(&v);
}

// ---------------------------------------------------------------------------
// Convert kernel: fp32 -> single fp16.  sel: 0=x, 1..4=W[sel-1]
// ---------------------------------------------------------------------------
__global__ void __launch_bounds__(256)
tofp16_kernel(const float4* __restrict__ src4, int sel, int n4)
{
    int i = blockIdx.x * 256 + threadIdx.x;
    if (i >= n4) return;
    float4 v = src4[i];
    __half2* dst = (sel == 0) ? (__half2*)g_x16 : (__half2*)g_W16[sel - 1];
    dst[2 * i]     = __floats2half2_rn(v.x, v.y);
    dst[2 * i + 1] = __floats2half2_rn(v.z, v.w);
}

// ---------------------------------------------------------------------------
// fp16 HMMA GEMM: C[M,N] = (Ah [+ Al])[M,K] @ W16[N,K]^T + bias
// Block 128x128, BK=32, cp.async double buffer, 8 warps (4m x 2n).
// MODE: 0 = fp32 out, 3 = fp16 single out (scaled by oscale)
// ASPLIT: 1 = A has an exact lo-residual operand (2 MMAs), 0 = single A (1 MMA)
// ---------------------------------------------------------------------------
#define GBK   32
#define GROWB 80
#define GTILE (128 * GROWB)        // 10240
#define GEMM_SMEM2 (2 * 2 * GTILE) // 40960 (single-A)
#define GEMM_SMEM3 (2 * 3 * GTILE) // 61440 (split-A)

#define SCALE_Q (0.08838834764831845f * 1.4426950408889634f)   // 1/sqrt(128)*log2e

__device__ __forceinline__ void gemm_issue_tile(uint32_t dst, const __half* src,
                                                int kc, int tid)
{
#pragma unroll
    for (int j = 0; j < 2; j++) {
        int idx = tid + (j << 8);          // 0..511
        int row = idx >> 2, c = idx & 3;
        g2s16(dst + row * GROWB + c * 16,
              src + (size_t)row * DMODEL + kc + c * 8);
    }
}

template<int MODE, int ASPLIT>
__device__ __forceinline__ void gemm_mma_body(
    const __half* __restrict__ Ah, const __half* __restrict__ Al,
    const __half* __restrict__ B,
    const float* __restrict__ bias,
    float* __restrict__ outF, __half* __restrict__ outH16, float oscale)
{
    extern __shared__ char sm[];
    const uint32_t sb = smem_u32(sm);
    const int tid = threadIdx.x, wid = tid >> 5, lane = tid & 31;
    const int m0 = blockIdx.y * 128, n0 = blockIdx.x * 128;
    const int wm = wid & 3, wn = wid >> 2;
    const int NT = 2 + ASPLIT;               // tiles per stage
    const uint32_t STG = (uint32_t)(NT * GTILE);

    const __half* tA_h = Ah + (size_t)m0 * DMODEL;
    const __half* tA_l = ASPLIT ? (Al + (size_t)m0 * DMODEL) : nullptr;
    const __half* tB   = B  + (size_t)n0 * DMODEL;

    float acc[2][8][4];
#pragma unroll
    for (int i = 0; i < 2; i++)
#pragma unroll
        for (int j = 0; j < 8; j++)
#pragma unroll
            for (int k = 0; k < 4; k++) acc[i][j][k] = 0.0f;

    const uint32_t a_off = (uint32_t)((lane & 15) * GROWB + (lane >> 4) * 16);
    const uint32_t b_off = (uint32_t)(((lane & 7) + ((lane >> 4) << 3)) * GROWB
                                      + ((lane >> 3) & 1) * 16);

    gemm_issue_tile(sb + 0 * GTILE, tA_h, 0, tid);
    if (ASPLIT) gemm_issue_tile(sb + 1 * GTILE, tA_l, 0, tid);
    gemm_issue_tile(sb + (1 + ASPLIT) * GTILE, tB, 0, tid);
    cp_commit();

    const int NCH = DMODEL / GBK;   // 64
    for (int ch = 0; ch < NCH; ch++) {
        if (ch + 1 < NCH) {
            uint32_t d = sb + ((ch + 1) & 1) * STG;
            int kc = (ch + 1) * GBK;
            gemm_issue_tile(d + 0 * GTILE, tA_h, kc, tid);
            if (ASPLIT) gemm_issue_tile(d + 1 * GTILE, tA_l, kc, tid);
            gemm_issue_tile(d + (1 + ASPLIT) * GTILE, tB, kc, tid);
            cp_commit();
            cp_wait<1>();
        } else {
            cp_wait<0>();
        }
        __syncthreads();

        const uint32_t stg = sb + (ch & 1) * STG;
        const uint32_t aH_b = stg + 0 * GTILE + (wm * 32) * GROWB + a_off;
        const uint32_t aL_b = stg + 1 * GTILE + (wm * 32) * GROWB + a_off;
        const uint32_t bS_b = stg + (1 + ASPLIT) * GTILE + (wn * 64) * GROWB + b_off;

#pragma unroll
        for (int ks = 0; ks < 2; ks++) {
            uint32_t aH[2][4], aL[2][4];
#pragma unroll
            for (int mt = 0; mt < 2; mt++) {
                ldm_x4(aH[mt], aH_b + mt * 16 * GROWB + ks * 32);
                if (ASPLIT) ldm_x4(aL[mt], aL_b + mt * 16 * GROWB + ks * 32);
            }
#pragma unroll
            for (int ntp = 0; ntp < 4; ntp++) {
                uint32_t bh[4];
                ldm_x4(bh, bS_b + ntp * 16 * GROWB + ks * 32);
#pragma unroll
                for (int mt = 0; mt < 2; mt++) {
                    mma_f16(acc[mt][2 * ntp],     aH[mt], bh[0], bh[1]);
                    mma_f16(acc[mt][2 * ntp + 1], aH[mt], bh[2], bh[3]);
                    if (ASPLIT) {
                        mma_f16(acc[mt][2 * ntp],     aL[mt], bh[0], bh[1]);
                        mma_f16(acc[mt][2 * ntp + 1], aL[mt], bh[2], bh[3]);
                    }
                }
            }
        }
        __syncthreads();
    }

    // epilogue
    const int rin = lane >> 2, cin = (lane & 3) * 2;
#pragma unroll
    for (int mt = 0; mt < 2; mt++) {
#pragma unroll
        for (int nt = 0; nt < 8; nt++) {
            int r = m0 + wm * 32 + mt * 16 + rin;
            int c = n0 + wn * 64 + nt * 8 + cin;
            float b0 = bias[c], b1 = bias[c + 1];
            float v0 = acc[mt][nt][0] + b0;
            float v1 = acc[mt][nt][1] + b1;
            float v2 = acc[mt][nt][2] + b0;
            float v3 = acc[mt][nt][3] + b1;
            if (MODE == 0) {
                *(float2*)&outF[(size_t)r * DMODEL + c]       = make_float2(v0, v1);
                *(float2*)&outF[(size_t)(r + 8) * DMODEL + c] = make_float2(v2, v3);
            } else {
                *(uint32_t*)&outH16[(size_t)r * DMODEL + c] =
                    packh2(v0 * oscale, v1 * oscale);
                *(uint32_t*)&outH16[(size_t)(r + 8) * DMODEL + c] =
                    packh2(v2 * oscale, v3 * oscale);
            }
        }
    }
}

__global__ void __launch_bounds__(256)
qkv_mma(const float* __restrict__ bq, const float* __restrict__ bk,
        const float* __restrict__ bv)
{
    int z = blockIdx.z;
    if (z == 0)
        gemm_mma_body<3, 0>(g_x16, nullptr, g_W16[0], bq, nullptr, g_Q16, SCALE_Q);
    else if (z == 1)
        gemm_mma_body<3, 0>(g_x16, nullptr, g_W16[1], bk, nullptr, g_K16, 1.0f);
    else
        gemm_mma_body<3, 0>(g_x16, nullptr, g_W16[2], bv, nullptr, g_V16, 1.0f);
}

__global__ void __launch_bounds__(256)
out_mma(const float* __restrict__ bo, float* __restrict__ out)
{
    gemm_mma_body<0, 1>(g_Ah16, g_Al16, g_W16[3], bo, out, nullptr, 1.0f);
}

// ---------------------------------------------------------------------------
// Flash attention, fp16 HMMA: CTA = (128 q-rows, head). 8 warps.
// QK^T: single fp16 Q (pre-scaled) vs single K. PV: unsplit P vs single V.
// ---------------------------------------------------------------------------
#define FROWB 272
#define QTILE (128 * FROWB)        // 34816
#define KTILE (64 * FROWB)         // 17408
#define KVSTG (2 * KTILE)          // 34816 (K + V)
#define FL_SMEM (QTILE + 2 * KVSTG)   // 104448

__device__ __forceinline__ void fl_issue_tile(uint32_t dst, const __half* src,
                                              int row0, int coff, int tid)
{
#pragma unroll
    for (int j = 0; j < 4; j++) {
        int idx = tid + (j << 8);          // 0..1023
        int row = idx >> 4, c = idx & 15;
        g2s16(dst + row * FROWB + c * 16,
              src + (size_t)(row0 + row) * DMODEL + coff + c * 8);
    }
}

__global__ void __launch_bounds__(256) flash_mma()
{
    extern __shared__ char sm[];
    const uint32_t sb = smem_u32(sm);
    const int tid = threadIdx.x, wid = tid >> 5, lane = tid & 31;
    const int h = blockIdx.y, q0 = blockIdx.x * 128;
    const int coff = h * HD;

    const uint32_t Q_s  = sb;
    const uint32_t KV0  = sb + QTILE;

    // prologue: Q (128 rows x 128 cols fp16), then KV chunk 0
#pragma unroll
    for (int j = 0; j < 4; j++) {
        int idx = tid + (j << 8);          // 0..1023
        int row = idx >> 3, c = idx & 7;   // 128 rows x 8 chunks of 32B
        g2s16(Q_s + row * FROWB + c * 32,
              g_Q16 + (size_t)(q0 + row) * DMODEL + coff + c * 16);
        g2s16(Q_s + row * FROWB + c * 32 + 16,
              g_Q16 + (size_t)(q0 + row) * DMODEL + coff + c * 16 + 8);
    }
    cp_commit();
    fl_issue_tile(KV0 + 0 * KTILE, g_K16, 0, coff, tid);
    fl_issue_tile(KV0 + 1 * KTILE, g_V16, 0, coff, tid);
    cp_commit();

    float oacc[16][4];
#pragma unroll
    for (int i = 0; i < 16; i++)
#pragma unroll
        for (int j = 0; j < 4; j++) oacc[i][j] = 0.0f;
    float mrow0 = -1e30f, mrow1 = -1e30f, lrow0 = 0.0f, lrow1 = 0.0f;

    const int rbase = wid * 16;
    const uint32_t a_off = (uint32_t)((rbase + (lane & 15)) * FROWB + (lane >> 4) * 16);
    const uint32_t b_off = (uint32_t)(((lane & 7) + ((lane >> 4) << 3)) * FROWB
                                      + ((lane >> 3) & 1) * 16);
    const uint32_t v_off = (uint32_t)((lane & 15) * FROWB + (lane >> 4) * 16);

    const int NCH = S_LEN / 64;   // 64
    for (int ch = 0; ch < NCH; ch++) {
        if (ch + 1 < NCH) {
            uint32_t d = KV0 + ((ch + 1) & 1) * KVSTG;
            int kv0 = (ch + 1) * 64;
            fl_issue_tile(d + 0 * KTILE, g_K16, kv0, coff, tid);
            fl_issue_tile(d + 1 * KTILE, g_V16, kv0, coff, tid);
            cp_commit();
            cp_wait<1>();
        } else {
            cp_wait<0>();
        }
        __syncthreads();

        const uint32_t K_s = KV0 + (ch & 1) * KVSTG;
        const uint32_t V_s = K_s + KTILE;

        // ---- S = Q K^T (64 keys), single fp16 Q, scores already in log2 units ----
        float s[8][4];
#pragma unroll
        for (int i = 0; i < 8; i++)
#pragma unroll
            for (int j = 0; j < 4; j++) s[i][j] = 0.0f;

#pragma unroll
        for (int ks = 0; ks < 8; ks++) {
            uint32_t aH[4];
            ldm_x4(aH, Q_s + a_off + ks * 32);
#pragma unroll
            for (int ntp = 0; ntp < 4; ntp++) {
                uint32_t bh[4];
                ldm_x4(bh, K_s + b_off + ntp * 16 * FROWB + ks * 32);
                mma_f16(s[2 * ntp],     aH, bh[0], bh[1]);
                mma_f16(s[2 * ntp + 1], aH, bh[2], bh[3]);
            }
        }

        // ---- online softmax (rows lane>>2 and +8), base-2 domain ----
        float mx0 = -1e30f, mx1 = -1e30f;
#pragma unroll
        for (int nt = 0; nt < 8; nt++) {
            mx0 = fmaxf(mx0, fmaxf(s[nt][0], s[nt][1]));
            mx1 = fmaxf(mx1, fmaxf(s[nt][2], s[nt][3]));
        }
        mx0 = fmaxf(mx0, __shfl_xor_sync(0xffffffffu, mx0, 1));
        mx0 = fmaxf(mx0, __shfl_xor_sync(0xffffffffu, mx0, 2));
        mx1 = fmaxf(mx1, __shfl_xor_sync(0xffffffffu, mx1, 1));
        mx1 = fmaxf(mx1, __shfl_xor_sync(0xffffffffu, mx1, 2));
        float nm0 = fmaxf(mrow0, mx0), nm1 = fmaxf(mrow1, mx1);
        float al0 = fexp2(mrow0 - nm0), al1 = fexp2(mrow1 - nm1);
        mrow0 = nm0; mrow1 = nm1;
        float rs0 = 0.0f, rs1 = 0.0f;
#pragma unroll
        for (int nt = 0; nt < 8; nt++) {
            s[nt][0] = fexp2(s[nt][0] - nm0);
            s[nt][1] = fexp2(s[nt][1] - nm0);
            s[nt][2] = fexp2(s[nt][2] - nm1);
            s[nt][3] = fexp2(s[nt][3] - nm1);
            rs0 += s[nt][0] + s[nt][1];
            rs1 += s[nt][2] + s[nt][3];
        }
        rs0 += __shfl_xor_sync(0xffffffffu, rs0, 1);
        rs0 += __shfl_xor_sync(0xffffffffu, rs0, 2);
        rs1 += __shfl_xor_sync(0xffffffffu, rs1, 1);
        rs1 += __shfl_xor_sync(0xffffffffu, rs1, 2);
        lrow0 = lrow0 * al0 + rs0;
        lrow1 = lrow1 * al1 + rs1;
#pragma unroll
        for (int nt = 0; nt < 16; nt++) {
            oacc[nt][0] *= al0; oacc[nt][1] *= al0;
            oacc[nt][2] *= al1; oacc[nt][3] *= al1;
        }

        // ---- O += P V, unsplit fp16 P ----
#pragma unroll
        for (int ks = 0; ks < 4; ks++) {
            uint32_t pH[4];
            pH[0] = packh2(s[2 * ks][0],     s[2 * ks][1]);
            pH[1] = packh2(s[2 * ks][2],     s[2 * ks][3]);
            pH[2] = packh2(s[2 * ks + 1][0], s[2 * ks + 1][1]);
            pH[3] = packh2(s[2 * ks + 1][2], s[2 * ks + 1][3]);
#pragma unroll
            for (int dp = 0; dp < 8; dp++) {
                uint32_t bh[4];
                ldm_x4_t(bh, V_s + v_off + ks * 16 * FROWB + dp * 32);
                mma_f16(oacc[2 * dp],     pH, bh[0], bh[1]);
                mma_f16(oacc[2 * dp + 1], pH, bh[2], bh[3]);
            }
        }
        __syncthreads();
    }

    // epilogue: normalize, exact fp16 split for O-projection
    float inv0 = 1.0f / lrow0, inv1 = 1.0f / lrow1;
    int r0 = q0 + rbase + (lane >> 2);
    int cb = coff + (lane & 3) * 2;
#pragma unroll
    for (int nt = 0; nt < 16; nt++) {
        int c = cb + nt * 8;
        uint32_t hh, ll;
        split2h(oacc[nt][0] * inv0, oacc[nt][1] * inv0, hh, ll);
        *(uint32_t*)&g_Ah16[(size_t)r0 * DMODEL + c] = hh;
        *(uint32_t*)&g_Al16[(size_t)r0 * DMODEL + c] = ll;
        split2h(oacc[nt][2] * inv1, oacc[nt][3] * inv1, hh, ll);
        *(uint32_t*)&g_Ah16[(size_t)(r0 + 8) * DMODEL + c] = hh;
        *(uint32_t*)&g_Al16[(size_t)(r0 + 8) * DMODEL + c] = ll;
    }
}

// ---------------------------------------------------------------------------
extern "C" void kernel_launch(void* const* d_in, const int* in_sizes, int n_in,
                              void* d_out, int out_size)
{
    const float* x  = (const float*)d_in[0];
    const float* Wq = (const float*)d_in[1];
    const float* bq = (const float*)d_in[2];
    const float* Wk = (const float*)d_in[3];
    const float* bk = (const float*)d_in[4];
    const float* Wv = (const float*)d_in[5];
    const float* bv = (const float*)d_in[6];
    const float* Wo = (const float*)d_in[7];
    const float* bo = (const float*)d_in[8];
    float* out = (float*)d_out;

    cudaFuncSetAttribute(qkv_mma,   cudaFuncAttributeMaxDynamicSharedMemorySize, GEMM_SMEM2);
    cudaFuncSetAttribute(out_mma,   cudaFuncAttributeMaxDynamicSharedMemorySize, GEMM_SMEM3);
    cudaFuncSetAttribute(flash_mma, cudaFuncAttributeMaxDynamicSharedMemorySize, FL_SMEM);

    const int n4x = S_LEN * DMODEL / 4;
    const int n4w = DMODEL * DMODEL / 4;

    tofp16_kernel<<<n4x / 256, 256>>>((const float4*)x,  0, n4x);
    tofp16_kernel<<<n4w / 256, 256>>>((const float4*)Wq, 1, n4w);
    tofp16_kernel<<<n4w / 256, 256>>>((const float4*)Wk, 2, n4w);
    tofp16_kernel<<<n4w / 256, 256>>>((const float4*)Wv, 3, n4w);
    tofp16_kernel<<<n4w / 256, 256>>>((const float4*)Wo, 4, n4w);

    qkv_mma<<<dim3(DMODEL / 128, S_LEN / 128, 3), 256, GEMM_SMEM2>>>(bq, bk, bv);
    flash_mma<<<dim3(S_LEN / 128, NHEADS), 256, FL_SMEM>>>();
    out_mma<<<dim3(DMODEL / 128, S_LEN / 128), 256, GEMM_SMEM3>>>(bo, out);
}